// round 1
// baseline (speedup 1.0000x reference)
#include <cuda_runtime.h>
#include <math_constants.h>

#define N_ENT   100000
#define N_USR   50000
#define N_EDGE  1000000
#define C       64
#define N_FACT  4
#define N_RELM1 9
#define TEMPR   0.2f
// 1 / (2*sqrt(32))
#define INV_SCALE 0.08838834764831845f

// ---------------- scratch (device globals; no allocation) ----------------
__device__ __align__(16) float g_S[N_ENT * N_RELM1];
__device__ float g_max1[N_ENT], g_sum1[N_ENT], g_max2[N_ENT], g_sum2[N_ENT];
__device__ float g_sr[N_EDGE];    // score_r -> exp1 -> exp2 (reused)
__device__ float g_ht[N_EDGE];    // h.t dot -> score_trip (reused)
__device__ float g_mask[N_EDGE];  // kg_mask (persisted for hop 2)
__device__ __align__(16) float g_entA[N_ENT * C];   // current ent
__device__ __align__(16) float g_entB[N_ENT * C];   // ent aggregation target
__device__ __align__(16) float g_usrA[N_USR * C];
__device__ __align__(16) float g_usrB[N_USR * C];
__device__ __align__(16) float g_mix[N_USR * C];    // (1 + mix)
__device__ __align__(16) float g_V[N_RELM1 * C];    // V[r][c], pre-scaled
__device__ float g_wn2[N_RELM1];
__device__ __align__(16) float g_dw[N_FACT * C];    // softmax(att) @ weight

// ---------------- helpers ----------------
__device__ __forceinline__ void atomicMaxF(float* addr, float v) {
    if (v >= 0.0f) atomicMax((int*)addr, __float_as_int(v));
    else           atomicMin((unsigned int*)addr, __float_as_uint(v));
}

__device__ __forceinline__ void redAdd4(float* p, float4 v) {
    asm volatile("red.global.add.v4.f32 [%0], {%1,%2,%3,%4};"
                 :: "l"(p), "f"(v.x), "f"(v.y), "f"(v.z), "f"(v.w)
                 : "memory");
}

// ---------------- tiny precompute: V, wn2, disen_w, cor ----------------
__global__ void k_prep(const float* __restrict__ weight,
                       const float* __restrict__ kgW,
                       const float* __restrict__ att,
                       float* __restrict__ out_cor) {
    __shared__ float sW[C * C];          // kg_W_r
    __shared__ float sWk[N_RELM1 * C];   // weight @ kg_W_r
    int t = threadIdx.x;
    for (int i = t; i < C * C; i += blockDim.x) sW[i] = kgW[i];
    __syncthreads();
    for (int i = t; i < N_RELM1 * C; i += blockDim.x) {
        int r = i / C, k = i % C;
        float s = 0.f;
        for (int c = 0; c < C; c++) s += weight[r * C + c] * sW[c * C + k];
        sWk[i] = s;
    }
    __syncthreads();
    // V[r][c] = sum_k W[c][k] * Wk[r][k], pre-scaled by 1/(2*sqrt(32))
    for (int i = t; i < N_RELM1 * C; i += blockDim.x) {
        int r = i / C, c = i % C;
        float s = 0.f;
        for (int k = 0; k < C; k++) s += sW[c * C + k] * sWk[r * C + k];
        g_V[i] = s * INV_SCALE;
    }
    if (t < N_RELM1) {
        float s = 0.f;
        for (int c = 0; c < C; c++) { float w = weight[t * C + c]; s += w * w; }
        g_wn2[t] = s;
    }
    if (t >= 32 && t < 32 + N_FACT) {
        int f = t - 32;
        float a[N_RELM1]; float m = -CUDART_INF_F;
        for (int j = 0; j < N_RELM1; j++) { a[j] = att[f * N_RELM1 + j]; m = fmaxf(m, a[j]); }
        float ssum = 0.f;
        for (int j = 0; j < N_RELM1; j++) { a[j] = expf(a[j] - m); ssum += a[j]; }
        for (int j = 0; j < N_RELM1; j++) a[j] /= ssum;
        for (int c = 0; c < C; c++) {
            float s = 0.f;
            for (int j = 0; j < N_RELM1; j++) s += a[j] * weight[j * C + c];
            g_dw[f * C + c] = s;
        }
    }
    if (t == 64) {
        // cor: disen_T = att.T [9,4]; pos_r = ||row_norm||^2 (==1 numerically);
        // ttl_r = sum_j (disen_T @ att)[r][j] = sum_f att[f][r] * rowsum_f
        float rowsum[N_FACT];
        for (int f = 0; f < N_FACT; f++) {
            float s = 0.f;
            for (int j = 0; j < N_RELM1; j++) s += att[f * N_RELM1 + j];
            rowsum[f] = s;
        }
        float cor = 0.f;
        for (int r = 0; r < N_RELM1; r++) {
            float ss = 0.f, ttl = 0.f;
            for (int f = 0; f < N_FACT; f++) {
                float v = att[f * N_RELM1 + r];
                ss += v * v; ttl += v * rowsum[f];
            }
            float n = sqrtf(ss);
            float pos = 0.f;
            for (int f = 0; f < N_FACT; f++) {
                float v = att[f * N_RELM1 + r] / n; pos += v * v;
            }
            cor += (ttl - pos) / TEMPR;   // == -sum(log(exp(pos/T)/exp(ttl/T)))
        }
        *out_cor = cor;
    }
}

// ---------------- init segment reductions ----------------
__global__ void k_initseg() {
    int i = blockIdx.x * blockDim.x + threadIdx.x;
    if (i < N_ENT) {
        g_max1[i] = -CUDART_INF_F; g_max2[i] = -CUDART_INF_F;
        g_sum1[i] = 0.f;           g_sum2[i] = 0.f;
    }
}

// ---------------- S = entity_emb @ V^T (one warp per entity) ----------------
__global__ void k_S(const float* __restrict__ ent) {
    int w = (blockIdx.x * blockDim.x + threadIdx.x) >> 5;
    int lane = threadIdx.x & 31;
    if (w >= N_ENT) return;
    float2 e = reinterpret_cast<const float2*>(ent + (size_t)w * C)[lane];
#pragma unroll
    for (int r = 0; r < N_RELM1; r++) {
        float2 v = reinterpret_cast<const float2*>(g_V + r * C)[lane];
        float p = e.x * v.x + e.y * v.y;
#pragma unroll
        for (int o = 16; o; o >>= 1) p += __shfl_xor_sync(0xffffffffu, p, o);
        if (lane == r) g_S[w * N_RELM1 + r] = p;
    }
}

// ---------------- edge scalar passes ----------------
__global__ void k_scoreA(const int* __restrict__ head, const int* __restrict__ etype) {
    int e = blockIdx.x * blockDim.x + threadIdx.x;
    if (e >= N_EDGE) return;
    int h = head[e], t = etype[e] - 1;
    float s = g_S[h * N_RELM1 + t];
    g_sr[e] = s;
    atomicMaxF(&g_max1[h], s);
}

__global__ void k_ht(const int* __restrict__ head, const int* __restrict__ tail,
                     const float* __restrict__ ent) {
    int gid = blockIdx.x * blockDim.x + threadIdx.x;
    int e = gid >> 4, s = gid & 15;
    if (e >= N_EDGE) return;
    int h = head[e], t = tail[e];
    float4 a = reinterpret_cast<const float4*>(ent)[(size_t)h * 16 + s];
    float4 b = reinterpret_cast<const float4*>(ent)[(size_t)t * 16 + s];
    float p = a.x * b.x + a.y * b.y + a.z * b.z + a.w * b.w;
    p += __shfl_xor_sync(0xffffffffu, p, 1);
    p += __shfl_xor_sync(0xffffffffu, p, 2);
    p += __shfl_xor_sync(0xffffffffu, p, 4);
    p += __shfl_xor_sync(0xffffffffu, p, 8);
    if (s == 0) g_ht[e] = p;
}

__global__ void k_exps1(const int* __restrict__ head) {
    int e = blockIdx.x * blockDim.x + threadIdx.x;
    if (e >= N_EDGE) return;
    int h = head[e];
    float e1 = expf(g_sr[e] - g_max1[h]);
    g_sr[e] = e1;
    atomicAdd(&g_sum1[h], e1);
}

__global__ void k_trip(const int* __restrict__ head, const int* __restrict__ etype) {
    int e = blockIdx.x * blockDim.x + threadIdx.x;
    if (e >= N_EDGE) return;
    int h = head[e], t = etype[e] - 1;
    float rs = g_sr[e] / (g_sum1[h] + 1e-16f);
    float tr = g_ht[e] + rs * rs * g_wn2[t];
    g_ht[e] = tr;
    atomicMaxF(&g_max2[h], tr);
}

__global__ void k_exps2(const int* __restrict__ head) {
    int e = blockIdx.x * blockDim.x + threadIdx.x;
    if (e >= N_EDGE) return;
    int h = head[e];
    float e2 = expf(g_ht[e] - g_max2[h]);
    g_sr[e] = e2;
    atomicAdd(&g_sum2[h], e2);
}

// ---------------- zero aggregation buffers ----------------
__global__ void k_zero() {
    int i = blockIdx.x * blockDim.x + threadIdx.x;
    float4 z = make_float4(0.f, 0.f, 0.f, 0.f);
    if (i < N_ENT * 16) reinterpret_cast<float4*>(g_entB)[i] = z;
    if (i < N_USR * 16) reinterpret_cast<float4*>(g_usrB)[i] = z;
}

// ---------------- KG scatter aggregation ----------------
template <bool FIRST, bool EXT>
__global__ void k_kgagg(const int* __restrict__ head, const int* __restrict__ tail,
                        const int* __restrict__ etype, const float* __restrict__ weight,
                        const float* __restrict__ ent_ext) {
    int gid = blockIdx.x * blockDim.x + threadIdx.x;
    int e = gid >> 4, s = gid & 15;
    if (e >= N_EDGE) return;
    int h = head[e], t = tail[e], r = etype[e] - 1;
    float m;
    if (FIRST) {
        m = g_sr[e] / (g_sum2[h] + 1e-16f);
        if (s == 0) g_mask[e] = m;
    } else {
        m = g_mask[e];
    }
    const float* src = EXT ? ent_ext : g_entA;
    float4 tv = reinterpret_cast<const float4*>(src)[(size_t)t * 16 + s];
    float4 wv = reinterpret_cast<const float4*>(weight)[r * 16 + s];
    float4 v;
    v.x = tv.x * wv.x * m; v.y = tv.y * wv.y * m;
    v.z = tv.z * wv.z * m; v.w = tv.w * wv.w * m;
    redAdd4(g_entB + ((size_t)h * C + s * 4), v);
}

// ---------------- user mix: (1 + sum_f softmax(u . latent)_f * disen_w_f) ----------------
template <bool EXT>
__global__ void k_mix(const float* __restrict__ usr_ext, const float* __restrict__ latent) {
    int w = (blockIdx.x * blockDim.x + threadIdx.x) >> 5;
    int lane = threadIdx.x & 31;
    if (w >= N_USR) return;
    const float* src = EXT ? usr_ext : g_usrA;
    float2 u = reinterpret_cast<const float2*>(src + (size_t)w * C)[lane];
    float d[N_FACT];
#pragma unroll
    for (int f = 0; f < N_FACT; f++) {
        float2 l = reinterpret_cast<const float2*>(latent + f * C)[lane];
        float p = u.x * l.x + u.y * l.y;
#pragma unroll
        for (int o = 16; o; o >>= 1) p += __shfl_xor_sync(0xffffffffu, p, o);
        d[f] = p;
    }
    float m = fmaxf(fmaxf(d[0], d[1]), fmaxf(d[2], d[3]));
    float ssum = 0.f;
#pragma unroll
    for (int f = 0; f < N_FACT; f++) { d[f] = expf(d[f] - m); ssum += d[f]; }
    float inv = 1.f / ssum;
    float2 mix; mix.x = 1.f; mix.y = 1.f;
#pragma unroll
    for (int f = 0; f < N_FACT; f++) {
        float2 dw = reinterpret_cast<const float2*>(g_dw + f * C)[lane];
        float p = d[f] * inv;
        mix.x += p * dw.x; mix.y += p * dw.y;
    }
    reinterpret_cast<float2*>(g_mix + (size_t)w * C)[lane] = mix;
}

// ---------------- UI scatter aggregation ----------------
template <bool EXT>
__global__ void k_uiagg(const int* __restrict__ rows, const int* __restrict__ cols,
                        const float* __restrict__ vals, const float* __restrict__ ent_ext) {
    int gid = blockIdx.x * blockDim.x + threadIdx.x;
    int e = gid >> 4, s = gid & 15;
    if (e >= N_EDGE) return;
    int rr = rows[e], cc = cols[e];
    float v = vals[e];
    const float* src = EXT ? ent_ext : g_entA;
    float4 t = reinterpret_cast<const float4*>(src)[(size_t)cc * 16 + s];
    float4 out;
    out.x = t.x * v; out.y = t.y * v; out.z = t.z * v; out.w = t.w * v;
    redAdd4(g_usrB + ((size_t)rr * C + s * 4), out);
}

// ---------------- normalize + accumulate residual ----------------
__global__ void k_entnorm(float* __restrict__ out_ent) {
    int w = (blockIdx.x * blockDim.x + threadIdx.x) >> 5;
    int lane = threadIdx.x & 31;
    if (w >= N_ENT) return;
    float2 x = reinterpret_cast<const float2*>(g_entB + (size_t)w * C)[lane];
    float ss = x.x * x.x + x.y * x.y;
#pragma unroll
    for (int o = 16; o; o >>= 1) ss += __shfl_xor_sync(0xffffffffu, ss, o);
    float inv = 1.f / fmaxf(sqrtf(ss), 1e-12f);
    x.x *= inv; x.y *= inv;
    reinterpret_cast<float2*>(g_entA + (size_t)w * C)[lane] = x;
    float2 o2 = reinterpret_cast<const float2*>(out_ent + (size_t)w * C)[lane];
    o2.x += x.x; o2.y += x.y;
    reinterpret_cast<float2*>(out_ent + (size_t)w * C)[lane] = o2;
}

__global__ void k_usrnorm(float* __restrict__ out_usr) {
    int w = (blockIdx.x * blockDim.x + threadIdx.x) >> 5;
    int lane = threadIdx.x & 31;
    if (w >= N_USR) return;
    float2 a = reinterpret_cast<const float2*>(g_usrB + (size_t)w * C)[lane];
    float2 m = reinterpret_cast<const float2*>(g_mix + (size_t)w * C)[lane];
    float2 x; x.x = a.x * m.x; x.y = a.y * m.y;
    float ss = x.x * x.x + x.y * x.y;
#pragma unroll
    for (int o = 16; o; o >>= 1) ss += __shfl_xor_sync(0xffffffffu, ss, o);
    float inv = 1.f / fmaxf(sqrtf(ss), 1e-12f);
    x.x *= inv; x.y *= inv;
    reinterpret_cast<float2*>(g_usrA + (size_t)w * C)[lane] = x;
    float2 o2 = reinterpret_cast<const float2*>(out_usr + (size_t)w * C)[lane];
    o2.x += x.x; o2.y += x.y;
    reinterpret_cast<float2*>(out_usr + (size_t)w * C)[lane] = o2;
}

// ---------------- launch ----------------
extern "C" void kernel_launch(void* const* d_in, const int* in_sizes, int n_in,
                              void* d_out, int out_size) {
    const float* user_emb   = (const float*)d_in[0];
    const float* entity_emb = (const float*)d_in[1];
    const float* latent     = (const float*)d_in[2];
    const float* weight     = (const float*)d_in[3];
    const float* att        = (const float*)d_in[4];
    const float* kgW        = (const float*)d_in[5];
    const float* ui_vals    = (const float*)d_in[6];
    const int*   edge_index = (const int*)d_in[7];
    const int*   etype      = (const int*)d_in[8];
    const int*   ui_rows    = (const int*)d_in[9];
    const int*   ui_cols    = (const int*)d_in[10];

    const int* head = edge_index;
    const int* tail = edge_index + N_EDGE;

    float* out      = (float*)d_out;
    float* out_ent  = out;
    float* out_usr  = out + (size_t)N_ENT * C;
    float* out_cor  = out + (size_t)N_ENT * C + (size_t)N_USR * C;

    const int TB = 256;
    dim3 gE((N_EDGE + TB - 1) / TB);           // 1 thread / edge
    dim3 gE16((N_EDGE * 16 + TB - 1) / TB);    // 16 threads / edge
    dim3 gEntW((N_ENT * 32 + TB - 1) / TB);    // warp / entity
    dim3 gUsrW((N_USR * 32 + TB - 1) / TB);    // warp / user
    dim3 gZero((N_ENT * 16 + TB - 1) / TB);
    dim3 gSeg((N_ENT + TB - 1) / TB);

    k_prep<<<1, 256>>>(weight, kgW, att, out_cor);
    k_initseg<<<gSeg, TB>>>();
    k_S<<<gEntW, TB>>>(entity_emb);
    k_scoreA<<<gE, TB>>>(head, etype);
    k_ht<<<gE16, TB>>>(head, tail, entity_emb);
    k_exps1<<<gE, TB>>>(head);
    k_trip<<<gE, TB>>>(head, etype);
    k_exps2<<<gE, TB>>>(head);

    cudaMemcpyAsync(out_ent, entity_emb, (size_t)N_ENT * C * sizeof(float),
                    cudaMemcpyDeviceToDevice, 0);
    cudaMemcpyAsync(out_usr, user_emb, (size_t)N_USR * C * sizeof(float),
                    cudaMemcpyDeviceToDevice, 0);

    // ---- hop 0 (reads input embeddings) ----
    k_zero<<<gZero, TB>>>();
    k_kgagg<true, true><<<gE16, TB>>>(head, tail, etype, weight, entity_emb);
    k_mix<true><<<gUsrW, TB>>>(user_emb, latent);
    k_uiagg<true><<<gE16, TB>>>(ui_rows, ui_cols, ui_vals, entity_emb);
    k_entnorm<<<gEntW, TB>>>(out_ent);
    k_usrnorm<<<gUsrW, TB>>>(out_usr);

    // ---- hop 1 (reads g_entA / g_usrA) ----
    k_zero<<<gZero, TB>>>();
    k_kgagg<false, false><<<gE16, TB>>>(head, tail, etype, weight, nullptr);
    k_mix<false><<<gUsrW, TB>>>(nullptr, latent);
    k_uiagg<false><<<gE16, TB>>>(ui_rows, ui_cols, ui_vals, nullptr);
    k_entnorm<<<gEntW, TB>>>(out_ent);
    k_usrnorm<<<gUsrW, TB>>>(out_usr);
}

// round 2
// speedup vs baseline: 1.0111x; 1.0111x over previous
#include <cuda_runtime.h>
#include <math_constants.h>

#define N_ENT   100000
#define N_USR   50000
#define N_EDGE  1000000
#define C       64
#define N_FACT  4
#define N_RELM1 9
#define TEMPR   0.2f
// 1 / (2*sqrt(32))
#define INV_SCALE 0.08838834764831845f

// ---------------- scratch (device globals; no allocation) ----------------
__device__ __align__(16) float g_V[N_RELM1 * C];     // W W^T w^T, pre-scaled
__device__ float g_wn2[N_RELM1];
__device__ __align__(16) float g_dw[N_FACT * C];     // softmax(att) @ weight
__device__ __align__(16) float g_entA[N_ENT * C];    // ent after hop0 norm
__device__ __align__(16) float g_usrA[N_USR * C];    // usr after hop0 norm
__device__ float g_mask[N_EDGE];                     // unnormalized e2 per CSR pos
__device__ int g_cntE[N_ENT], g_offE[N_ENT], g_curE[N_ENT];
__device__ int g_cntU[N_USR], g_offU[N_USR], g_curU[N_USR];
__device__ int g_eidxE[N_EDGE], g_eidxU[N_EDGE];

// ---------------- tiny precompute: V, wn2, disen_w, cor ----------------
__global__ void k_prep(const float* __restrict__ weight,
                       const float* __restrict__ kgW,
                       const float* __restrict__ att,
                       float* __restrict__ out_cor) {
    __shared__ float sW[C * C];          // kg_W_r
    __shared__ float sWk[N_RELM1 * C];   // weight @ kg_W_r
    int t = threadIdx.x;
    for (int i = t; i < C * C; i += blockDim.x) sW[i] = kgW[i];
    __syncthreads();
    for (int i = t; i < N_RELM1 * C; i += blockDim.x) {
        int r = i / C, k = i % C;
        float s = 0.f;
        for (int c = 0; c < C; c++) s += weight[r * C + c] * sW[c * C + k];
        sWk[i] = s;
    }
    __syncthreads();
    // V[r][c] = sum_k W[c][k] * Wk[r][k], pre-scaled by 1/(2*sqrt(32))
    for (int i = t; i < N_RELM1 * C; i += blockDim.x) {
        int r = i / C, c = i % C;
        float s = 0.f;
        for (int k = 0; k < C; k++) s += sW[c * C + k] * sWk[r * C + k];
        g_V[i] = s * INV_SCALE;
    }
    if (t < N_RELM1) {
        float s = 0.f;
        for (int c = 0; c < C; c++) { float w = weight[t * C + c]; s += w * w; }
        g_wn2[t] = s;
    }
    if (t >= 32 && t < 32 + N_FACT) {
        int f = t - 32;
        float a[N_RELM1]; float m = -CUDART_INF_F;
        for (int j = 0; j < N_RELM1; j++) { a[j] = att[f * N_RELM1 + j]; m = fmaxf(m, a[j]); }
        float ssum = 0.f;
        for (int j = 0; j < N_RELM1; j++) { a[j] = expf(a[j] - m); ssum += a[j]; }
        for (int j = 0; j < N_RELM1; j++) a[j] /= ssum;
        for (int c = 0; c < C; c++) {
            float s = 0.f;
            for (int j = 0; j < N_RELM1; j++) s += a[j] * weight[j * C + c];
            g_dw[f * C + c] = s;
        }
    }
    if (t == 64) {
        float rowsum[N_FACT];
        for (int f = 0; f < N_FACT; f++) {
            float s = 0.f;
            for (int j = 0; j < N_RELM1; j++) s += att[f * N_RELM1 + j];
            rowsum[f] = s;
        }
        float cor = 0.f;
        for (int r = 0; r < N_RELM1; r++) {
            float ss = 0.f, ttl = 0.f;
            for (int f = 0; f < N_FACT; f++) {
                float v = att[f * N_RELM1 + r];
                ss += v * v; ttl += v * rowsum[f];
            }
            float n = sqrtf(ss);
            float pos = 0.f;
            for (int f = 0; f < N_FACT; f++) {
                float v = att[f * N_RELM1 + r] / n; pos += v * v;
            }
            cor += (ttl - pos) / TEMPR;
        }
        *out_cor = cor;
    }
}

// ---------------- CSR build ----------------
__global__ void k_zcnt() {
    int i = blockIdx.x * blockDim.x + threadIdx.x;
    if (i < N_ENT) g_cntE[i] = 0;
    if (i < N_USR) g_cntU[i] = 0;
}

__global__ void k_count(const int* __restrict__ head, const int* __restrict__ urows) {
    int e = blockIdx.x * blockDim.x + threadIdx.x;
    if (e >= N_EDGE) return;
    atomicAdd(&g_cntE[head[e]], 1);
    atomicAdd(&g_cntU[urows[e]], 1);
}

__global__ void k_scan() {
    // blockIdx 0 -> entity CSR, blockIdx 1 -> user CSR
    const int n   = (blockIdx.x == 0) ? N_ENT : N_USR;
    int* cnt = (blockIdx.x == 0) ? g_cntE : g_cntU;
    int* off = (blockIdx.x == 0) ? g_offE : g_offU;
    int* cur = (blockIdx.x == 0) ? g_curE : g_curU;
    __shared__ int part[1024];
    int t = threadIdx.x;
    int per = (n + 1023) / 1024;
    int base = t * per;
    int s = 0;
    for (int i = 0; i < per; i++) { int j = base + i; if (j < n) s += cnt[j]; }
    part[t] = s;
    __syncthreads();
    for (int d = 1; d < 1024; d <<= 1) {
        int v = (t >= d) ? part[t - d] : 0;
        __syncthreads();
        part[t] += v;
        __syncthreads();
    }
    int run = (t == 0) ? 0 : part[t - 1];
    for (int i = 0; i < per; i++) {
        int j = base + i;
        if (j < n) { off[j] = run; cur[j] = run; run += cnt[j]; }
    }
}

__global__ void k_fill(const int* __restrict__ head, const int* __restrict__ urows) {
    int e = blockIdx.x * blockDim.x + threadIdx.x;
    if (e >= N_EDGE) return;
    int p = atomicAdd(&g_curE[head[e]], 1);
    g_eidxE[p] = e;
    int q = atomicAdd(&g_curU[urows[e]], 1);
    g_eidxU[q] = e;
}

// ---------------- helpers ----------------
__device__ __forceinline__ float dot4(float4 a, float4 b) {
    return a.x * b.x + a.y * b.y + a.z * b.z + a.w * b.w;
}
__device__ __forceinline__ float red16(float p, unsigned m) {
    p += __shfl_xor_sync(m, p, 1);
    p += __shfl_xor_sync(m, p, 2);
    p += __shfl_xor_sync(m, p, 4);
    p += __shfl_xor_sync(m, p, 8);
    return p;
}

// ---------------- KG hop 0: softmax chain + aggregate + norm + residual ----------------
// warp per head; half-warps process alternate edges (float4/lane over 16 lanes = 64 cols)
__global__ void __launch_bounds__(256) k_kg0(const float* __restrict__ ent,
                                             const int* __restrict__ tail,
                                             const int* __restrict__ etype,
                                             const float* __restrict__ weight,
                                             float* __restrict__ out_ent) {
    __shared__ float4 sV[N_RELM1 * 16];
    __shared__ float4 sW[N_RELM1 * 16];
    __shared__ float  sWn[N_RELM1];
    int t = threadIdx.x;
    for (int i = t; i < N_RELM1 * 16; i += 256) {
        sV[i] = reinterpret_cast<const float4*>(g_V)[i];
        sW[i] = reinterpret_cast<const float4*>(weight)[i];
    }
    if (t < N_RELM1) sWn[t] = g_wn2[t];
    __syncthreads();

    int w = blockIdx.x * 8 + (t >> 5);
    if (w >= N_ENT) return;
    int lane = t & 31, half = lane >> 4, l = lane & 15;
    unsigned hm = 0xFFFFu << (half * 16);
    int off = g_offE[w], deg = g_cntE[w];

    float4 hv = reinterpret_cast<const float4*>(ent)[(size_t)w * 16 + l];

    // pass 1: sum1 = sum exp(score_r)
    float s1 = 0.f;
    for (int i = half; i < deg; i += 2) {
        int e  = g_eidxE[off + i];
        int ty = etype[e] - 1;
        float p = red16(dot4(hv, sV[ty * 16 + l]), hm);
        s1 += expf(p);
    }
    __syncwarp();
    s1 += __shfl_xor_sync(0xffffffffu, s1, 16);
    float inv1 = 1.f / (s1 + 1e-16f);

    // pass 2: e2 per edge (store as unnormalized mask), accumulate masked messages
    float4 acc = make_float4(0.f, 0.f, 0.f, 0.f);
    for (int i = half; i < deg; i += 2) {
        int e  = g_eidxE[off + i];
        int ty = etype[e] - 1;
        int tl = tail[e];
        float4 tv = reinterpret_cast<const float4*>(ent)[(size_t)tl * 16 + l];
        float p  = red16(dot4(hv, sV[ty * 16 + l]), hm);
        float ht = red16(dot4(hv, tv), hm);
        float rs = expf(p) * inv1;
        float e2 = expf(ht + rs * rs * sWn[ty]);
        float4 wv = sW[ty * 16 + l];
        acc.x += e2 * tv.x * wv.x;
        acc.y += e2 * tv.y * wv.y;
        acc.z += e2 * tv.z * wv.z;
        acc.w += e2 * tv.w * wv.w;
        if (l == 0) g_mask[off + i] = e2;   // per-head uniform 1/sum2 cancels under l2norm
    }
    __syncwarp();
    acc.x += __shfl_xor_sync(0xffffffffu, acc.x, 16);
    acc.y += __shfl_xor_sync(0xffffffffu, acc.y, 16);
    acc.z += __shfl_xor_sync(0xffffffffu, acc.z, 16);
    acc.w += __shfl_xor_sync(0xffffffffu, acc.w, 16);

    float ss = red16(dot4(acc, acc), 0xffffffffu);
    float inv = 1.f / fmaxf(sqrtf(ss), 1e-12f);
    float4 x = make_float4(acc.x * inv, acc.y * inv, acc.z * inv, acc.w * inv);
    if (half == 0) {
        reinterpret_cast<float4*>(g_entA)[(size_t)w * 16 + l] = x;
        float4 o = make_float4(hv.x + x.x, hv.y + x.y, hv.z + x.z, hv.w + x.w);
        reinterpret_cast<float4*>(out_ent)[(size_t)w * 16 + l] = o;
    }
}

// ---------------- KG hop 1: mask-weighted aggregate + norm + residual ----------------
__global__ void __launch_bounds__(256) k_kg1(const int* __restrict__ tail,
                                             const int* __restrict__ etype,
                                             const float* __restrict__ weight,
                                             float* __restrict__ out_ent) {
    __shared__ float4 sW[N_RELM1 * 16];
    int t = threadIdx.x;
    for (int i = t; i < N_RELM1 * 16; i += 256)
        sW[i] = reinterpret_cast<const float4*>(weight)[i];
    __syncthreads();

    int w = blockIdx.x * 8 + (t >> 5);
    if (w >= N_ENT) return;
    int lane = t & 31, half = lane >> 4, l = lane & 15;
    int off = g_offE[w], deg = g_cntE[w];

    float4 acc = make_float4(0.f, 0.f, 0.f, 0.f);
    for (int i = half; i < deg; i += 2) {
        int e  = g_eidxE[off + i];
        float m = g_mask[off + i];
        int ty = etype[e] - 1;
        int tl = tail[e];
        float4 tv = reinterpret_cast<const float4*>(g_entA)[(size_t)tl * 16 + l];
        float4 wv = sW[ty * 16 + l];
        acc.x += m * tv.x * wv.x;
        acc.y += m * tv.y * wv.y;
        acc.z += m * tv.z * wv.z;
        acc.w += m * tv.w * wv.w;
    }
    __syncwarp();
    acc.x += __shfl_xor_sync(0xffffffffu, acc.x, 16);
    acc.y += __shfl_xor_sync(0xffffffffu, acc.y, 16);
    acc.z += __shfl_xor_sync(0xffffffffu, acc.z, 16);
    acc.w += __shfl_xor_sync(0xffffffffu, acc.w, 16);

    float ss = red16(dot4(acc, acc), 0xffffffffu);
    float inv = 1.f / fmaxf(sqrtf(ss), 1e-12f);
    if (half == 0) {
        float4 o = reinterpret_cast<const float4*>(out_ent)[(size_t)w * 16 + l];
        o.x += acc.x * inv; o.y += acc.y * inv;
        o.z += acc.z * inv; o.w += acc.w * inv;
        reinterpret_cast<float4*>(out_ent)[(size_t)w * 16 + l] = o;
    }
}

// ---------------- UI hop: aggregate + mix + norm + residual ----------------
template <int HOP>
__global__ void __launch_bounds__(256) k_ui(const float* __restrict__ user_emb,
                                            const float* __restrict__ entity_emb,
                                            const float* __restrict__ latent,
                                            const float* __restrict__ vals,
                                            const int* __restrict__ cols,
                                            float* __restrict__ out_usr) {
    __shared__ float4 sL[N_FACT * 16];
    __shared__ float4 sD[N_FACT * 16];
    int t = threadIdx.x;
    for (int i = t; i < N_FACT * 16; i += 256) {
        sL[i] = reinterpret_cast<const float4*>(latent)[i];
        sD[i] = reinterpret_cast<const float4*>(g_dw)[i];
    }
    __syncthreads();

    int u = blockIdx.x * 8 + (t >> 5);
    if (u >= N_USR) return;
    int lane = t & 31, half = lane >> 4, l = lane & 15;
    unsigned hm = 0xFFFFu << (half * 16);
    const float* usr_src = (HOP == 0) ? user_emb : g_usrA;
    const float* ent_src = (HOP == 0) ? entity_emb : g_entA;

    float4 uv = reinterpret_cast<const float4*>(usr_src)[(size_t)u * 16 + l];

    // mix = 1 + sum_f softmax(u . latent)_f * dw_f
    float d0 = red16(dot4(uv, sL[0 * 16 + l]), hm);
    float d1 = red16(dot4(uv, sL[1 * 16 + l]), hm);
    float d2 = red16(dot4(uv, sL[2 * 16 + l]), hm);
    float d3 = red16(dot4(uv, sL[3 * 16 + l]), hm);
    float m = fmaxf(fmaxf(d0, d1), fmaxf(d2, d3));
    d0 = expf(d0 - m); d1 = expf(d1 - m); d2 = expf(d2 - m); d3 = expf(d3 - m);
    float invs = 1.f / (d0 + d1 + d2 + d3);
    d0 *= invs; d1 *= invs; d2 *= invs; d3 *= invs;
    float4 a0 = sD[0 * 16 + l], a1 = sD[1 * 16 + l], a2 = sD[2 * 16 + l], a3 = sD[3 * 16 + l];
    float4 mix;
    mix.x = 1.f + d0 * a0.x + d1 * a1.x + d2 * a2.x + d3 * a3.x;
    mix.y = 1.f + d0 * a0.y + d1 * a1.y + d2 * a2.y + d3 * a3.y;
    mix.z = 1.f + d0 * a0.z + d1 * a1.z + d2 * a2.z + d3 * a3.z;
    mix.w = 1.f + d0 * a0.w + d1 * a1.w + d2 * a2.w + d3 * a3.w;

    int off = g_offU[u], deg = g_cntU[u];
    float4 acc = make_float4(0.f, 0.f, 0.f, 0.f);
    for (int i = half; i < deg; i += 2) {
        int e = g_eidxU[off + i];
        float v = vals[e];
        int c = cols[e];
        float4 tv = reinterpret_cast<const float4*>(ent_src)[(size_t)c * 16 + l];
        acc.x += v * tv.x; acc.y += v * tv.y;
        acc.z += v * tv.z; acc.w += v * tv.w;
    }
    __syncwarp();
    acc.x += __shfl_xor_sync(0xffffffffu, acc.x, 16);
    acc.y += __shfl_xor_sync(0xffffffffu, acc.y, 16);
    acc.z += __shfl_xor_sync(0xffffffffu, acc.z, 16);
    acc.w += __shfl_xor_sync(0xffffffffu, acc.w, 16);

    float4 x = make_float4(acc.x * mix.x, acc.y * mix.y, acc.z * mix.z, acc.w * mix.w);
    float ss = red16(dot4(x, x), 0xffffffffu);
    float inv = 1.f / fmaxf(sqrtf(ss), 1e-12f);
    x.x *= inv; x.y *= inv; x.z *= inv; x.w *= inv;

    if (half == 0) {
        if (HOP == 0) {
            reinterpret_cast<float4*>(g_usrA)[(size_t)u * 16 + l] = x;
            float4 o = make_float4(uv.x + x.x, uv.y + x.y, uv.z + x.z, uv.w + x.w);
            reinterpret_cast<float4*>(out_usr)[(size_t)u * 16 + l] = o;
        } else {
            float4 o = reinterpret_cast<const float4*>(out_usr)[(size_t)u * 16 + l];
            o.x += x.x; o.y += x.y; o.z += x.z; o.w += x.w;
            reinterpret_cast<float4*>(out_usr)[(size_t)u * 16 + l] = o;
        }
    }
}

// ---------------- launch ----------------
extern "C" void kernel_launch(void* const* d_in, const int* in_sizes, int n_in,
                              void* d_out, int out_size) {
    const float* user_emb   = (const float*)d_in[0];
    const float* entity_emb = (const float*)d_in[1];
    const float* latent     = (const float*)d_in[2];
    const float* weight     = (const float*)d_in[3];
    const float* att        = (const float*)d_in[4];
    const float* kgW        = (const float*)d_in[5];
    const float* ui_vals    = (const float*)d_in[6];
    const int*   edge_index = (const int*)d_in[7];
    const int*   etype      = (const int*)d_in[8];
    const int*   ui_rows    = (const int*)d_in[9];
    const int*   ui_cols    = (const int*)d_in[10];

    const int* head = edge_index;
    const int* tail = edge_index + N_EDGE;

    float* out     = (float*)d_out;
    float* out_ent = out;
    float* out_usr = out + (size_t)N_ENT * C;
    float* out_cor = out + (size_t)N_ENT * C + (size_t)N_USR * C;

    const int TB = 256;
    dim3 gE((N_EDGE + TB - 1) / TB);
    dim3 gZ((N_ENT + TB - 1) / TB);
    dim3 gKG((N_ENT * 32 + TB - 1) / TB);   // warp per entity
    dim3 gUI((N_USR * 32 + TB - 1) / TB);   // warp per user

    k_prep<<<1, 256>>>(weight, kgW, att, out_cor);
    k_zcnt<<<gZ, TB>>>();
    k_count<<<gE, TB>>>(head, ui_rows);
    k_scan<<<2, 1024>>>();
    k_fill<<<gE, TB>>>(head, ui_rows);

    k_kg0<<<gKG, TB>>>(entity_emb, tail, etype, weight, out_ent);
    k_ui<0><<<gUI, TB>>>(user_emb, entity_emb, latent, ui_vals, ui_cols, out_usr);
    k_ui<1><<<gUI, TB>>>(user_emb, entity_emb, latent, ui_vals, ui_cols, out_usr);
    k_kg1<<<gKG, TB>>>(tail, etype, weight, out_ent);
}

// round 4
// speedup vs baseline: 1.4842x; 1.4678x over previous
#include <cuda_runtime.h>
#include <math_constants.h>

#define N_ENT   100000
#define N_USR   50000
#define N_EDGE  1000000
#define C       64
#define N_FACT  4
#define N_RELM1 9
#define TEMPR   0.2f
// 1 / (2*sqrt(32))
#define INV_SCALE 0.08838834764831845f

#define SCAN_B  1024
#define NB_E    ((N_ENT + SCAN_B - 1) / SCAN_B)   // 98
#define NB_U    ((N_USR + SCAN_B - 1) / SCAN_B)   // 49

// ---------------- scratch (device globals; no allocation) ----------------
__device__ __align__(16) float g_V[N_RELM1 * C];     // W W^T w^T, pre-scaled
__device__ float g_wn2[N_RELM1];
__device__ __align__(16) float g_dw[N_FACT * C];     // softmax(att) @ weight
__device__ __align__(16) float g_entA[N_ENT * C];    // ent after hop0 norm
__device__ __align__(16) float g_usrA[N_USR * C];    // usr after hop0 norm
__device__ float g_mask[N_EDGE];                     // unnormalized e2 per CSR pos
__device__ int g_cntE[N_ENT], g_offE[N_ENT], g_curE[N_ENT];
__device__ int g_cntU[N_USR], g_offU[N_USR], g_curU[N_USR];
__device__ int g_eidxE[N_EDGE], g_eidxU[N_EDGE];
__device__ int g_bsumE[128], g_bpreE[128];
__device__ int g_bsumU[128], g_bpreU[128];

// ---------------- tiny precompute: V, wn2, disen_w, cor ----------------
__global__ void k_prep(const float* __restrict__ weight,
                       const float* __restrict__ kgW,
                       const float* __restrict__ att,
                       float* __restrict__ out_cor) {
    __shared__ float sW[C * C];          // kg_W_r
    __shared__ float sWk[N_RELM1 * C];   // weight @ kg_W_r
    int t = threadIdx.x;
    for (int i = t; i < C * C; i += blockDim.x) sW[i] = kgW[i];
    __syncthreads();
    for (int i = t; i < N_RELM1 * C; i += blockDim.x) {
        int r = i / C, k = i % C;
        float s = 0.f;
        for (int c = 0; c < C; c++) s += weight[r * C + c] * sW[c * C + k];
        sWk[i] = s;
    }
    __syncthreads();
    for (int i = t; i < N_RELM1 * C; i += blockDim.x) {
        int r = i / C, c = i % C;
        float s = 0.f;
        for (int k = 0; k < C; k++) s += sW[c * C + k] * sWk[r * C + k];
        g_V[i] = s * INV_SCALE;
    }
    if (t < N_RELM1) {
        float s = 0.f;
        for (int c = 0; c < C; c++) { float w = weight[t * C + c]; s += w * w; }
        g_wn2[t] = s;
    }
    if (t >= 32 && t < 32 + N_FACT) {
        int f = t - 32;
        float a[N_RELM1]; float m = -CUDART_INF_F;
        for (int j = 0; j < N_RELM1; j++) { a[j] = att[f * N_RELM1 + j]; m = fmaxf(m, a[j]); }
        float ssum = 0.f;
        for (int j = 0; j < N_RELM1; j++) { a[j] = expf(a[j] - m); ssum += a[j]; }
        for (int j = 0; j < N_RELM1; j++) a[j] /= ssum;
        for (int c = 0; c < C; c++) {
            float s = 0.f;
            for (int j = 0; j < N_RELM1; j++) s += a[j] * weight[j * C + c];
            g_dw[f * C + c] = s;
        }
    }
    if (t == 64) {
        float rowsum[N_FACT];
        for (int f = 0; f < N_FACT; f++) {
            float s = 0.f;
            for (int j = 0; j < N_RELM1; j++) s += att[f * N_RELM1 + j];
            rowsum[f] = s;
        }
        float cor = 0.f;
        for (int r = 0; r < N_RELM1; r++) {
            float ss = 0.f, ttl = 0.f;
            for (int f = 0; f < N_FACT; f++) {
                float v = att[f * N_RELM1 + r];
                ss += v * v; ttl += v * rowsum[f];
            }
            float n = sqrtf(ss);
            float pos = 0.f;
            for (int f = 0; f < N_FACT; f++) {
                float v = att[f * N_RELM1 + r] / n; pos += v * v;
            }
            cor += (ttl - pos) / TEMPR;
        }
        *out_cor = cor;
    }
}

// ---------------- CSR build ----------------
__global__ void k_zcnt() {
    int i = blockIdx.x * blockDim.x + threadIdx.x;
    if (i < N_ENT) g_cntE[i] = 0;
    if (i < N_USR) g_cntU[i] = 0;
}

__global__ void k_count(const int* __restrict__ head, const int* __restrict__ urows) {
    int e = blockIdx.x * blockDim.x + threadIdx.x;
    if (e >= N_EDGE) return;
    atomicAdd(&g_cntE[head[e]], 1);
    atomicAdd(&g_cntU[urows[e]], 1);
}

// phase 1: per-block exclusive scan, record block sums
__global__ void k_scan1() {
    __shared__ int sh[SCAN_B];
    bool isE = blockIdx.x < NB_E;
    int b = isE ? blockIdx.x : blockIdx.x - NB_E;
    int n = isE ? N_ENT : N_USR;
    int* cnt = isE ? g_cntE : g_cntU;
    int* off = isE ? g_offE : g_offU;
    int* bsum = isE ? g_bsumE : g_bsumU;
    int t = threadIdx.x;
    int i = b * SCAN_B + t;
    int v = (i < n) ? cnt[i] : 0;
    sh[t] = v;
    __syncthreads();
    for (int d = 1; d < SCAN_B; d <<= 1) {
        int u = (t >= d) ? sh[t - d] : 0;
        __syncthreads();
        sh[t] += u;
        __syncthreads();
    }
    if (i < n) off[i] = sh[t] - v;   // exclusive within block
    if (t == SCAN_B - 1) bsum[b] = sh[t];
}

// phase 2: scan block sums (single block)
__global__ void k_scan2() {
    __shared__ int sh[128];
    int t = threadIdx.x;
    int v = (t < NB_E) ? g_bsumE[t] : 0;
    sh[t] = v;
    __syncthreads();
    for (int d = 1; d < 128; d <<= 1) {
        int u = (t >= d) ? sh[t - d] : 0;
        __syncthreads();
        sh[t] += u;
        __syncthreads();
    }
    if (t < NB_E) g_bpreE[t] = sh[t] - v;
    __syncthreads();
    int w = (t < NB_U) ? g_bsumU[t] : 0;
    sh[t] = w;
    __syncthreads();
    for (int d = 1; d < 128; d <<= 1) {
        int u = (t >= d) ? sh[t - d] : 0;
        __syncthreads();
        sh[t] += u;
        __syncthreads();
    }
    if (t < NB_U) g_bpreU[t] = sh[t] - w;
}

// phase 3: add block prefix, init cursors
__global__ void k_scan3() {
    bool isE = blockIdx.x < NB_E;
    int b = isE ? blockIdx.x : blockIdx.x - NB_E;
    int n = isE ? N_ENT : N_USR;
    int* off = isE ? g_offE : g_offU;
    int* cur = isE ? g_curE : g_curU;
    const int* bpre = isE ? g_bpreE : g_bpreU;
    int i = b * SCAN_B + threadIdx.x;
    if (i < n) {
        int o = off[i] + bpre[b];
        off[i] = o;
        cur[i] = o;
    }
}

__global__ void k_fill(const int* __restrict__ head, const int* __restrict__ urows) {
    int e = blockIdx.x * blockDim.x + threadIdx.x;
    if (e >= N_EDGE) return;
    int p = atomicAdd(&g_curE[head[e]], 1);
    g_eidxE[p] = e;
    int q = atomicAdd(&g_curU[urows[e]], 1);
    g_eidxU[q] = e;
}

// ---------------- helpers ----------------
__device__ __forceinline__ float dot4(float4 a, float4 b) {
    return a.x * b.x + a.y * b.y + a.z * b.z + a.w * b.w;
}
__device__ __forceinline__ float red16(float p, unsigned m) {
    p += __shfl_xor_sync(m, p, 1);
    p += __shfl_xor_sync(m, p, 2);
    p += __shfl_xor_sync(m, p, 4);
    p += __shfl_xor_sync(m, p, 8);
    return p;
}

// ---------------- KG hop 0 ----------------
// warp per head; half-warps process alternate edges (float4/lane over 16 lanes)
// relation scores depend only on (head,type): computed once per head, one per lane.
__global__ void __launch_bounds__(256) k_kg0(const float* __restrict__ ent,
                                             const int* __restrict__ tail,
                                             const int* __restrict__ etype,
                                             const float* __restrict__ weight,
                                             float* __restrict__ out_ent) {
    __shared__ float4 sV[N_RELM1 * 16];
    __shared__ float4 sW[N_RELM1 * 16];
    __shared__ float  sWn[N_RELM1];
    int t = threadIdx.x;
    for (int i = t; i < N_RELM1 * 16; i += 256) {
        sV[i] = reinterpret_cast<const float4*>(g_V)[i];
        sW[i] = reinterpret_cast<const float4*>(weight)[i];
    }
    if (t < N_RELM1) sWn[t] = g_wn2[t];
    __syncthreads();

    int w = blockIdx.x * 8 + (t >> 5);
    if (w >= N_ENT) return;
    int lane = t & 31, half = lane >> 4, l = lane & 15;
    unsigned hm = 0xFFFFu << (half * 16);
    int off = g_offE[w], deg = g_cntE[w];

    float4 hv = __ldg(&reinterpret_cast<const float4*>(ent)[(size_t)w * 16 + l]);

    // per-relation exp(score): lane r (within each half) holds exp(hv . V_r)
    float me = 0.f;
#pragma unroll
    for (int r = 0; r < N_RELM1; r++) {
        float p = red16(dot4(hv, sV[r * 16 + l]), hm);
        if (l == r) me = expf(p);
    }

    // pass 1: sum1 = sum_e exp(score[ty_e])  (half-mask: loop is half-divergent)
    float s1 = 0.f;
    for (int i = half; i < deg; i += 2) {
        int e  = __ldg(&g_eidxE[off + i]);
        int ty = __ldg(&etype[e]) - 1;
        s1 += __shfl_sync(hm, me, ty, 16);
    }
    __syncwarp();
    s1 += __shfl_xor_sync(0xffffffffu, s1, 16);
    float inv1 = 1.f / (s1 + 1e-16f);

    // pass 2: e2 per edge (unnormalized; 1/sum2 cancels under l2norm), aggregate
    float4 acc = make_float4(0.f, 0.f, 0.f, 0.f);
    for (int i = half; i < deg; i += 2) {
        int e  = __ldg(&g_eidxE[off + i]);
        int ty = __ldg(&etype[e]) - 1;
        int tl = __ldg(&tail[e]);
        float4 tv = __ldg(&reinterpret_cast<const float4*>(ent)[(size_t)tl * 16 + l]);
        float es = __shfl_sync(hm, me, ty, 16);
        float ht = red16(dot4(hv, tv), hm);
        float rs = es * inv1;
        float e2 = expf(ht + rs * rs * sWn[ty]);
        float4 wv = sW[ty * 16 + l];
        acc.x += e2 * tv.x * wv.x;
        acc.y += e2 * tv.y * wv.y;
        acc.z += e2 * tv.z * wv.z;
        acc.w += e2 * tv.w * wv.w;
        if (l == 0) g_mask[off + i] = e2;
    }
    __syncwarp();
    acc.x += __shfl_xor_sync(0xffffffffu, acc.x, 16);
    acc.y += __shfl_xor_sync(0xffffffffu, acc.y, 16);
    acc.z += __shfl_xor_sync(0xffffffffu, acc.z, 16);
    acc.w += __shfl_xor_sync(0xffffffffu, acc.w, 16);

    float ss = red16(dot4(acc, acc), 0xffffffffu);
    float inv = 1.f / fmaxf(sqrtf(ss), 1e-12f);
    float4 x = make_float4(acc.x * inv, acc.y * inv, acc.z * inv, acc.w * inv);
    if (half == 0) {
        reinterpret_cast<float4*>(g_entA)[(size_t)w * 16 + l] = x;
        float4 o = make_float4(hv.x + x.x, hv.y + x.y, hv.z + x.z, hv.w + x.w);
        reinterpret_cast<float4*>(out_ent)[(size_t)w * 16 + l] = o;
    }
}

// ---------------- KG hop 1 ----------------
__global__ void __launch_bounds__(256) k_kg1(const int* __restrict__ tail,
                                             const int* __restrict__ etype,
                                             const float* __restrict__ weight,
                                             float* __restrict__ out_ent) {
    __shared__ float4 sW[N_RELM1 * 16];
    int t = threadIdx.x;
    for (int i = t; i < N_RELM1 * 16; i += 256)
        sW[i] = reinterpret_cast<const float4*>(weight)[i];
    __syncthreads();

    int w = blockIdx.x * 8 + (t >> 5);
    if (w >= N_ENT) return;
    int lane = t & 31, half = lane >> 4, l = lane & 15;
    int off = g_offE[w], deg = g_cntE[w];

    float4 acc = make_float4(0.f, 0.f, 0.f, 0.f);
    for (int i = half; i < deg; i += 2) {
        int e  = __ldg(&g_eidxE[off + i]);
        float m = __ldg(&g_mask[off + i]);
        int ty = __ldg(&etype[e]) - 1;
        int tl = __ldg(&tail[e]);
        float4 tv = __ldg(&reinterpret_cast<const float4*>(g_entA)[(size_t)tl * 16 + l]);
        float4 wv = sW[ty * 16 + l];
        acc.x += m * tv.x * wv.x;
        acc.y += m * tv.y * wv.y;
        acc.z += m * tv.z * wv.z;
        acc.w += m * tv.w * wv.w;
    }
    __syncwarp();
    acc.x += __shfl_xor_sync(0xffffffffu, acc.x, 16);
    acc.y += __shfl_xor_sync(0xffffffffu, acc.y, 16);
    acc.z += __shfl_xor_sync(0xffffffffu, acc.z, 16);
    acc.w += __shfl_xor_sync(0xffffffffu, acc.w, 16);

    float ss = red16(dot4(acc, acc), 0xffffffffu);
    float inv = 1.f / fmaxf(sqrtf(ss), 1e-12f);
    if (half == 0) {
        float4 o = reinterpret_cast<const float4*>(out_ent)[(size_t)w * 16 + l];
        o.x += acc.x * inv; o.y += acc.y * inv;
        o.z += acc.z * inv; o.w += acc.w * inv;
        reinterpret_cast<float4*>(out_ent)[(size_t)w * 16 + l] = o;
    }
}

// ---------------- UI hop ----------------
template <int HOP>
__global__ void __launch_bounds__(256) k_ui(const float* __restrict__ user_emb,
                                            const float* __restrict__ entity_emb,
                                            const float* __restrict__ latent,
                                            const float* __restrict__ vals,
                                            const int* __restrict__ cols,
                                            float* __restrict__ out_usr) {
    __shared__ float4 sL[N_FACT * 16];
    __shared__ float4 sD[N_FACT * 16];
    int t = threadIdx.x;
    for (int i = t; i < N_FACT * 16; i += 256) {
        sL[i] = reinterpret_cast<const float4*>(latent)[i];
        sD[i] = reinterpret_cast<const float4*>(g_dw)[i];
    }
    __syncthreads();

    int u = blockIdx.x * 8 + (t >> 5);
    if (u >= N_USR) return;
    int lane = t & 31, half = lane >> 4, l = lane & 15;
    unsigned hm = 0xFFFFu << (half * 16);
    const float* usr_src = (HOP == 0) ? user_emb : g_usrA;
    const float* ent_src = (HOP == 0) ? entity_emb : g_entA;

    float4 uv = __ldg(&reinterpret_cast<const float4*>(usr_src)[(size_t)u * 16 + l]);

    float d0 = red16(dot4(uv, sL[0 * 16 + l]), hm);
    float d1 = red16(dot4(uv, sL[1 * 16 + l]), hm);
    float d2 = red16(dot4(uv, sL[2 * 16 + l]), hm);
    float d3 = red16(dot4(uv, sL[3 * 16 + l]), hm);
    float m = fmaxf(fmaxf(d0, d1), fmaxf(d2, d3));
    d0 = expf(d0 - m); d1 = expf(d1 - m); d2 = expf(d2 - m); d3 = expf(d3 - m);
    float invs = 1.f / (d0 + d1 + d2 + d3);
    d0 *= invs; d1 *= invs; d2 *= invs; d3 *= invs;
    float4 a0 = sD[0 * 16 + l], a1 = sD[1 * 16 + l], a2 = sD[2 * 16 + l], a3 = sD[3 * 16 + l];
    float4 mix;
    mix.x = 1.f + d0 * a0.x + d1 * a1.x + d2 * a2.x + d3 * a3.x;
    mix.y = 1.f + d0 * a0.y + d1 * a1.y + d2 * a2.y + d3 * a3.y;
    mix.z = 1.f + d0 * a0.z + d1 * a1.z + d2 * a2.z + d3 * a3.z;
    mix.w = 1.f + d0 * a0.w + d1 * a1.w + d2 * a2.w + d3 * a3.w;

    int off = g_offU[u], deg = g_cntU[u];
    float4 acc = make_float4(0.f, 0.f, 0.f, 0.f);
    for (int i = half; i < deg; i += 2) {
        int e = __ldg(&g_eidxU[off + i]);
        float v = __ldg(&vals[e]);
        int c = __ldg(&cols[e]);
        float4 tv = __ldg(&reinterpret_cast<const float4*>(ent_src)[(size_t)c * 16 + l]);
        acc.x += v * tv.x; acc.y += v * tv.y;
        acc.z += v * tv.z; acc.w += v * tv.w;
    }
    __syncwarp();
    acc.x += __shfl_xor_sync(0xffffffffu, acc.x, 16);
    acc.y += __shfl_xor_sync(0xffffffffu, acc.y, 16);
    acc.z += __shfl_xor_sync(0xffffffffu, acc.z, 16);
    acc.w += __shfl_xor_sync(0xffffffffu, acc.w, 16);

    float4 x = make_float4(acc.x * mix.x, acc.y * mix.y, acc.z * mix.z, acc.w * mix.w);
    float ss = red16(dot4(x, x), 0xffffffffu);
    float inv = 1.f / fmaxf(sqrtf(ss), 1e-12f);
    x.x *= inv; x.y *= inv; x.z *= inv; x.w *= inv;

    if (half == 0) {
        if (HOP == 0) {
            reinterpret_cast<float4*>(g_usrA)[(size_t)u * 16 + l] = x;
            float4 o = make_float4(uv.x + x.x, uv.y + x.y, uv.z + x.z, uv.w + x.w);
            reinterpret_cast<float4*>(out_usr)[(size_t)u * 16 + l] = o;
        } else {
            float4 o = reinterpret_cast<const float4*>(out_usr)[(size_t)u * 16 + l];
            o.x += x.x; o.y += x.y; o.z += x.z; o.w += x.w;
            reinterpret_cast<float4*>(out_usr)[(size_t)u * 16 + l] = o;
        }
    }
}

// ---------------- launch ----------------
extern "C" void kernel_launch(void* const* d_in, const int* in_sizes, int n_in,
                              void* d_out, int out_size) {
    const float* user_emb   = (const float*)d_in[0];
    const float* entity_emb = (const float*)d_in[1];
    const float* latent     = (const float*)d_in[2];
    const float* weight     = (const float*)d_in[3];
    const float* att        = (const float*)d_in[4];
    const float* kgW        = (const float*)d_in[5];
    const float* ui_vals    = (const float*)d_in[6];
    const int*   edge_index = (const int*)d_in[7];
    const int*   etype      = (const int*)d_in[8];
    const int*   ui_rows    = (const int*)d_in[9];
    const int*   ui_cols    = (const int*)d_in[10];

    const int* head = edge_index;
    const int* tail = edge_index + N_EDGE;

    float* out     = (float*)d_out;
    float* out_ent = out;
    float* out_usr = out + (size_t)N_ENT * C;
    float* out_cor = out + (size_t)N_ENT * C + (size_t)N_USR * C;

    const int TB = 256;
    dim3 gE((N_EDGE + TB - 1) / TB);
    dim3 gZ((N_ENT + TB - 1) / TB);
    dim3 gKG((N_ENT * 32 + TB - 1) / TB);
    dim3 gUI((N_USR * 32 + TB - 1) / TB);

    k_prep<<<1, 256>>>(weight, kgW, att, out_cor);
    k_zcnt<<<gZ, TB>>>();
    k_count<<<gE, TB>>>(head, ui_rows);
    k_scan1<<<NB_E + NB_U, SCAN_B>>>();
    k_scan2<<<1, 128>>>();
    k_scan3<<<NB_E + NB_U, SCAN_B>>>();
    k_fill<<<gE, TB>>>(head, ui_rows);

    k_kg0<<<gKG, TB>>>(entity_emb, tail, etype, weight, out_ent);
    k_ui<0><<<gUI, TB>>>(user_emb, entity_emb, latent, ui_vals, ui_cols, out_usr);
    k_ui<1><<<gUI, TB>>>(user_emb, entity_emb, latent, ui_vals, ui_cols, out_usr);
    k_kg1<<<gKG, TB>>>(tail, etype, weight, out_ent);
}

// round 5
// speedup vs baseline: 1.8301x; 1.2331x over previous
#include <cuda_runtime.h>
#include <math_constants.h>

#define N_ENT   100000
#define N_USR   50000
#define N_EDGE  1000000
#define C       64
#define N_FACT  4
#define N_RELM1 9
#define TEMPR   0.2f
// 1 / (2*sqrt(32))
#define INV_SCALE 0.08838834764831845f

#define SCAN_B  1024
#define NB_E    ((N_ENT + SCAN_B - 1) / SCAN_B)   // 98
#define NB_U    ((N_USR + SCAN_B - 1) / SCAN_B)   // 49

// ---------------- scratch (device globals; no allocation) ----------------
__device__ __align__(16) float g_V[N_RELM1 * C];     // W W^T w^T, pre-scaled
__device__ float g_wn2[N_RELM1];
__device__ __align__(16) float g_dw[N_FACT * C];     // softmax(att) @ weight
__device__ __align__(16) float g_entA[N_ENT * C];    // ent after hop0 norm
__device__ __align__(16) float g_usrA[N_USR * C];    // usr after hop0 norm
__device__ float g_mask[N_EDGE];                     // unnormalized e2 per CSR pos
__device__ int g_cntE[N_ENT], g_offE[N_ENT], g_curE[N_ENT];
__device__ int g_cntU[N_USR], g_offU[N_USR], g_curU[N_USR];
__device__ int   g_pkE[N_EDGE];    // CSR-ordered packed (tail | type<<20)
__device__ int   g_colU[N_EDGE];   // CSR-ordered ui_cols
__device__ float g_valU[N_EDGE];   // CSR-ordered ui_vals
__device__ int g_bsumE[128], g_bpreE[128];
__device__ int g_bsumU[128], g_bpreU[128];

// ---------------- tiny precompute: V, wn2, disen_w, cor ----------------
__global__ void k_prep(const float* __restrict__ weight,
                       const float* __restrict__ kgW,
                       const float* __restrict__ att,
                       float* __restrict__ out_cor) {
    __shared__ float sW[C * C];          // kg_W_r
    __shared__ float sWk[N_RELM1 * C];   // weight @ kg_W_r
    int t = threadIdx.x;
    for (int i = t; i < C * C; i += blockDim.x) sW[i] = kgW[i];
    __syncthreads();
    for (int i = t; i < N_RELM1 * C; i += blockDim.x) {
        int r = i / C, k = i % C;
        float s = 0.f;
        for (int c = 0; c < C; c++) s += weight[r * C + c] * sW[c * C + k];
        sWk[i] = s;
    }
    __syncthreads();
    for (int i = t; i < N_RELM1 * C; i += blockDim.x) {
        int r = i / C, c = i % C;
        float s = 0.f;
        for (int k = 0; k < C; k++) s += sW[c * C + k] * sWk[r * C + k];
        g_V[i] = s * INV_SCALE;
    }
    if (t < N_RELM1) {
        float s = 0.f;
        for (int c = 0; c < C; c++) { float w = weight[t * C + c]; s += w * w; }
        g_wn2[t] = s;
    }
    if (t >= 32 && t < 32 + N_FACT) {
        int f = t - 32;
        float a[N_RELM1]; float m = -CUDART_INF_F;
        for (int j = 0; j < N_RELM1; j++) { a[j] = att[f * N_RELM1 + j]; m = fmaxf(m, a[j]); }
        float ssum = 0.f;
        for (int j = 0; j < N_RELM1; j++) { a[j] = expf(a[j] - m); ssum += a[j]; }
        for (int j = 0; j < N_RELM1; j++) a[j] /= ssum;
        for (int c = 0; c < C; c++) {
            float s = 0.f;
            for (int j = 0; j < N_RELM1; j++) s += a[j] * weight[j * C + c];
            g_dw[f * C + c] = s;
        }
    }
    if (t == 64) {
        float rowsum[N_FACT];
        for (int f = 0; f < N_FACT; f++) {
            float s = 0.f;
            for (int j = 0; j < N_RELM1; j++) s += att[f * N_RELM1 + j];
            rowsum[f] = s;
        }
        float cor = 0.f;
        for (int r = 0; r < N_RELM1; r++) {
            float ss = 0.f, ttl = 0.f;
            for (int f = 0; f < N_FACT; f++) {
                float v = att[f * N_RELM1 + r];
                ss += v * v; ttl += v * rowsum[f];
            }
            float n = sqrtf(ss);
            float pos = 0.f;
            for (int f = 0; f < N_FACT; f++) {
                float v = att[f * N_RELM1 + r] / n; pos += v * v;
            }
            cor += (ttl - pos) / TEMPR;
        }
        *out_cor = cor;
    }
}

// ---------------- CSR build ----------------
__global__ void k_zcnt() {
    int i = blockIdx.x * blockDim.x + threadIdx.x;
    if (i < N_ENT) g_cntE[i] = 0;
    if (i < N_USR) g_cntU[i] = 0;
}

__global__ void k_count(const int* __restrict__ head, const int* __restrict__ urows) {
    int e = blockIdx.x * blockDim.x + threadIdx.x;
    if (e >= N_EDGE) return;
    atomicAdd(&g_cntE[head[e]], 1);
    atomicAdd(&g_cntU[urows[e]], 1);
}

// phase 1: per-block exclusive scan, record block sums
__global__ void k_scan1() {
    __shared__ int sh[SCAN_B];
    bool isE = blockIdx.x < NB_E;
    int b = isE ? blockIdx.x : blockIdx.x - NB_E;
    int n = isE ? N_ENT : N_USR;
    int* cnt = isE ? g_cntE : g_cntU;
    int* off = isE ? g_offE : g_offU;
    int* bsum = isE ? g_bsumE : g_bsumU;
    int t = threadIdx.x;
    int i = b * SCAN_B + t;
    int v = (i < n) ? cnt[i] : 0;
    sh[t] = v;
    __syncthreads();
    for (int d = 1; d < SCAN_B; d <<= 1) {
        int u = (t >= d) ? sh[t - d] : 0;
        __syncthreads();
        sh[t] += u;
        __syncthreads();
    }
    if (i < n) off[i] = sh[t] - v;   // exclusive within block
    if (t == SCAN_B - 1) bsum[b] = sh[t];
}

// phase 2: scan block sums (single block)
__global__ void k_scan2() {
    __shared__ int sh[128];
    int t = threadIdx.x;
    int v = (t < NB_E) ? g_bsumE[t] : 0;
    sh[t] = v;
    __syncthreads();
    for (int d = 1; d < 128; d <<= 1) {
        int u = (t >= d) ? sh[t - d] : 0;
        __syncthreads();
        sh[t] += u;
        __syncthreads();
    }
    if (t < NB_E) g_bpreE[t] = sh[t] - v;
    __syncthreads();
    int w = (t < NB_U) ? g_bsumU[t] : 0;
    sh[t] = w;
    __syncthreads();
    for (int d = 1; d < 128; d <<= 1) {
        int u = (t >= d) ? sh[t - d] : 0;
        __syncthreads();
        sh[t] += u;
        __syncthreads();
    }
    if (t < NB_U) g_bpreU[t] = sh[t] - w;
}

// phase 3: add block prefix, init cursors
__global__ void k_scan3() {
    bool isE = blockIdx.x < NB_E;
    int b = isE ? blockIdx.x : blockIdx.x - NB_E;
    int n = isE ? N_ENT : N_USR;
    int* off = isE ? g_offE : g_offU;
    int* cur = isE ? g_curE : g_curU;
    const int* bpre = isE ? g_bpreE : g_bpreU;
    int i = b * SCAN_B + threadIdx.x;
    if (i < n) {
        int o = off[i] + bpre[b];
        off[i] = o;
        cur[i] = o;
    }
}

// fill: materialize edge payloads in CSR order (removes random reads later)
__global__ void k_fill(const int* __restrict__ head, const int* __restrict__ tail,
                       const int* __restrict__ etype, const int* __restrict__ urows,
                       const int* __restrict__ ucols, const float* __restrict__ uvals) {
    int e = blockIdx.x * blockDim.x + threadIdx.x;
    if (e >= N_EDGE) return;
    int p = atomicAdd(&g_curE[head[e]], 1);
    g_pkE[p] = tail[e] | ((etype[e] - 1) << 20);
    int q = atomicAdd(&g_curU[urows[e]], 1);
    g_colU[q] = ucols[e];
    g_valU[q] = uvals[e];
}

// ---------------- helpers ----------------
__device__ __forceinline__ float dot4(float4 a, float4 b) {
    return a.x * b.x + a.y * b.y + a.z * b.z + a.w * b.w;
}
__device__ __forceinline__ float red16(float p, unsigned m) {
    p += __shfl_xor_sync(m, p, 1);
    p += __shfl_xor_sync(m, p, 2);
    p += __shfl_xor_sync(m, p, 4);
    p += __shfl_xor_sync(m, p, 8);
    return p;
}

// ---------------- KG hop 0 ----------------
__global__ void __launch_bounds__(256) k_kg0(const float* __restrict__ ent,
                                             const float* __restrict__ weight,
                                             float* __restrict__ out_ent) {
    __shared__ float4 sV[N_RELM1 * 16];
    __shared__ float4 sW[N_RELM1 * 16];
    __shared__ float  sWn[N_RELM1];
    int t = threadIdx.x;
    for (int i = t; i < N_RELM1 * 16; i += 256) {
        sV[i] = reinterpret_cast<const float4*>(g_V)[i];
        sW[i] = reinterpret_cast<const float4*>(weight)[i];
    }
    if (t < N_RELM1) sWn[t] = g_wn2[t];
    __syncthreads();

    int w = blockIdx.x * 8 + (t >> 5);
    if (w >= N_ENT) return;
    int lane = t & 31, half = lane >> 4, l = lane & 15;
    unsigned hm = 0xFFFFu << (half * 16);
    int off = g_offE[w], deg = g_cntE[w];

    float4 hv = __ldg(&reinterpret_cast<const float4*>(ent)[(size_t)w * 16 + l]);

    // per-relation exp(score): lane r (within each half) holds exp(hv . V_r)
    float me = 0.f;
#pragma unroll
    for (int r = 0; r < N_RELM1; r++) {
        float p = red16(dot4(hv, sV[r * 16 + l]), hm);
        if (l == r) me = expf(p);
    }

    // pass 1: sum1 over coalesced packed types
    float s1 = 0.f;
#pragma unroll 2
    for (int i = half; i < deg; i += 2) {
        int ty = __ldg(&g_pkE[off + i]) >> 20;
        s1 += __shfl_sync(hm, me, ty, 16);
    }
    __syncwarp();
    s1 += __shfl_xor_sync(0xffffffffu, s1, 16);
    float inv1 = 1.f / (s1 + 1e-16f);

    // pass 2: e2 per edge (unnormalized; 1/sum2 cancels under l2norm), aggregate
    float4 acc = make_float4(0.f, 0.f, 0.f, 0.f);
#pragma unroll 2
    for (int i = half; i < deg; i += 2) {
        int pk = __ldg(&g_pkE[off + i]);
        int ty = pk >> 20;
        int tl = pk & 0xFFFFF;
        float4 tv = __ldg(&reinterpret_cast<const float4*>(ent)[(size_t)tl * 16 + l]);
        float es = __shfl_sync(hm, me, ty, 16);
        float ht = red16(dot4(hv, tv), hm);
        float rs = es * inv1;
        float e2 = expf(ht + rs * rs * sWn[ty]);
        float4 wv = sW[ty * 16 + l];
        acc.x += e2 * tv.x * wv.x;
        acc.y += e2 * tv.y * wv.y;
        acc.z += e2 * tv.z * wv.z;
        acc.w += e2 * tv.w * wv.w;
        if (l == 0) g_mask[off + i] = e2;
    }
    __syncwarp();
    acc.x += __shfl_xor_sync(0xffffffffu, acc.x, 16);
    acc.y += __shfl_xor_sync(0xffffffffu, acc.y, 16);
    acc.z += __shfl_xor_sync(0xffffffffu, acc.z, 16);
    acc.w += __shfl_xor_sync(0xffffffffu, acc.w, 16);

    float ss = red16(dot4(acc, acc), 0xffffffffu);
    float inv = 1.f / fmaxf(sqrtf(ss), 1e-12f);
    float4 x = make_float4(acc.x * inv, acc.y * inv, acc.z * inv, acc.w * inv);
    if (half == 0) {
        reinterpret_cast<float4*>(g_entA)[(size_t)w * 16 + l] = x;
        float4 o = make_float4(hv.x + x.x, hv.y + x.y, hv.z + x.z, hv.w + x.w);
        reinterpret_cast<float4*>(out_ent)[(size_t)w * 16 + l] = o;
    }
}

// ---------------- KG hop 1 ----------------
__global__ void __launch_bounds__(256) k_kg1(const float* __restrict__ weight,
                                             float* __restrict__ out_ent) {
    __shared__ float4 sW[N_RELM1 * 16];
    int t = threadIdx.x;
    for (int i = t; i < N_RELM1 * 16; i += 256)
        sW[i] = reinterpret_cast<const float4*>(weight)[i];
    __syncthreads();

    int w = blockIdx.x * 8 + (t >> 5);
    if (w >= N_ENT) return;
    int lane = t & 31, half = lane >> 4, l = lane & 15;
    int off = g_offE[w], deg = g_cntE[w];

    float4 acc = make_float4(0.f, 0.f, 0.f, 0.f);
#pragma unroll 2
    for (int i = half; i < deg; i += 2) {
        int pk = __ldg(&g_pkE[off + i]);
        float m = __ldg(&g_mask[off + i]);
        int ty = pk >> 20;
        int tl = pk & 0xFFFFF;
        float4 tv = __ldg(&reinterpret_cast<const float4*>(g_entA)[(size_t)tl * 16 + l]);
        float4 wv = sW[ty * 16 + l];
        acc.x += m * tv.x * wv.x;
        acc.y += m * tv.y * wv.y;
        acc.z += m * tv.z * wv.z;
        acc.w += m * tv.w * wv.w;
    }
    __syncwarp();
    acc.x += __shfl_xor_sync(0xffffffffu, acc.x, 16);
    acc.y += __shfl_xor_sync(0xffffffffu, acc.y, 16);
    acc.z += __shfl_xor_sync(0xffffffffu, acc.z, 16);
    acc.w += __shfl_xor_sync(0xffffffffu, acc.w, 16);

    float ss = red16(dot4(acc, acc), 0xffffffffu);
    float inv = 1.f / fmaxf(sqrtf(ss), 1e-12f);
    if (half == 0) {
        float4 o = reinterpret_cast<const float4*>(out_ent)[(size_t)w * 16 + l];
        o.x += acc.x * inv; o.y += acc.y * inv;
        o.z += acc.z * inv; o.w += acc.w * inv;
        reinterpret_cast<float4*>(out_ent)[(size_t)w * 16 + l] = o;
    }
}

// ---------------- UI hop ----------------
template <int HOP>
__global__ void __launch_bounds__(256) k_ui(const float* __restrict__ user_emb,
                                            const float* __restrict__ entity_emb,
                                            const float* __restrict__ latent,
                                            float* __restrict__ out_usr) {
    __shared__ float4 sL[N_FACT * 16];
    __shared__ float4 sD[N_FACT * 16];
    int t = threadIdx.x;
    for (int i = t; i < N_FACT * 16; i += 256) {
        sL[i] = reinterpret_cast<const float4*>(latent)[i];
        sD[i] = reinterpret_cast<const float4*>(g_dw)[i];
    }
    __syncthreads();

    int u = blockIdx.x * 8 + (t >> 5);
    if (u >= N_USR) return;
    int lane = t & 31, half = lane >> 4, l = lane & 15;
    unsigned hm = 0xFFFFu << (half * 16);
    const float* usr_src = (HOP == 0) ? user_emb : g_usrA;
    const float* ent_src = (HOP == 0) ? entity_emb : g_entA;

    float4 uv = __ldg(&reinterpret_cast<const float4*>(usr_src)[(size_t)u * 16 + l]);

    float d0 = red16(dot4(uv, sL[0 * 16 + l]), hm);
    float d1 = red16(dot4(uv, sL[1 * 16 + l]), hm);
    float d2 = red16(dot4(uv, sL[2 * 16 + l]), hm);
    float d3 = red16(dot4(uv, sL[3 * 16 + l]), hm);
    float m = fmaxf(fmaxf(d0, d1), fmaxf(d2, d3));
    d0 = expf(d0 - m); d1 = expf(d1 - m); d2 = expf(d2 - m); d3 = expf(d3 - m);
    float invs = 1.f / (d0 + d1 + d2 + d3);
    d0 *= invs; d1 *= invs; d2 *= invs; d3 *= invs;
    float4 a0 = sD[0 * 16 + l], a1 = sD[1 * 16 + l], a2 = sD[2 * 16 + l], a3 = sD[3 * 16 + l];
    float4 mix;
    mix.x = 1.f + d0 * a0.x + d1 * a1.x + d2 * a2.x + d3 * a3.x;
    mix.y = 1.f + d0 * a0.y + d1 * a1.y + d2 * a2.y + d3 * a3.y;
    mix.z = 1.f + d0 * a0.z + d1 * a1.z + d2 * a2.z + d3 * a3.z;
    mix.w = 1.f + d0 * a0.w + d1 * a1.w + d2 * a2.w + d3 * a3.w;

    int off = g_offU[u], deg = g_cntU[u];
    float4 acc = make_float4(0.f, 0.f, 0.f, 0.f);
#pragma unroll 2
    for (int i = half; i < deg; i += 2) {
        float v = __ldg(&g_valU[off + i]);
        int c = __ldg(&g_colU[off + i]);
        float4 tv = __ldg(&reinterpret_cast<const float4*>(ent_src)[(size_t)c * 16 + l]);
        acc.x += v * tv.x; acc.y += v * tv.y;
        acc.z += v * tv.z; acc.w += v * tv.w;
    }
    __syncwarp();
    acc.x += __shfl_xor_sync(0xffffffffu, acc.x, 16);
    acc.y += __shfl_xor_sync(0xffffffffu, acc.y, 16);
    acc.z += __shfl_xor_sync(0xffffffffu, acc.z, 16);
    acc.w += __shfl_xor_sync(0xffffffffu, acc.w, 16);

    float4 x = make_float4(acc.x * mix.x, acc.y * mix.y, acc.z * mix.z, acc.w * mix.w);
    float ss = red16(dot4(x, x), 0xffffffffu);
    float inv = 1.f / fmaxf(sqrtf(ss), 1e-12f);
    x.x *= inv; x.y *= inv; x.z *= inv; x.w *= inv;

    if (half == 0) {
        if (HOP == 0) {
            reinterpret_cast<float4*>(g_usrA)[(size_t)u * 16 + l] = x;
            float4 o = make_float4(uv.x + x.x, uv.y + x.y, uv.z + x.z, uv.w + x.w);
            reinterpret_cast<float4*>(out_usr)[(size_t)u * 16 + l] = o;
        } else {
            float4 o = reinterpret_cast<const float4*>(out_usr)[(size_t)u * 16 + l];
            o.x += x.x; o.y += x.y; o.z += x.z; o.w += x.w;
            reinterpret_cast<float4*>(out_usr)[(size_t)u * 16 + l] = o;
        }
    }
}

// ---------------- launch ----------------
extern "C" void kernel_launch(void* const* d_in, const int* in_sizes, int n_in,
                              void* d_out, int out_size) {
    const float* user_emb   = (const float*)d_in[0];
    const float* entity_emb = (const float*)d_in[1];
    const float* latent     = (const float*)d_in[2];
    const float* weight     = (const float*)d_in[3];
    const float* att        = (const float*)d_in[4];
    const float* kgW        = (const float*)d_in[5];
    const float* ui_vals    = (const float*)d_in[6];
    const int*   edge_index = (const int*)d_in[7];
    const int*   etype      = (const int*)d_in[8];
    const int*   ui_rows    = (const int*)d_in[9];
    const int*   ui_cols    = (const int*)d_in[10];

    const int* head = edge_index;
    const int* tail = edge_index + N_EDGE;

    float* out     = (float*)d_out;
    float* out_ent = out;
    float* out_usr = out + (size_t)N_ENT * C;
    float* out_cor = out + (size_t)N_ENT * C + (size_t)N_USR * C;

    const int TB = 256;
    dim3 gE((N_EDGE + TB - 1) / TB);
    dim3 gZ((N_ENT + TB - 1) / TB);
    dim3 gKG((N_ENT * 32 + TB - 1) / TB);
    dim3 gUI((N_USR * 32 + TB - 1) / TB);

    k_prep<<<1, 256>>>(weight, kgW, att, out_cor);
    k_zcnt<<<gZ, TB>>>();
    k_count<<<gE, TB>>>(head, ui_rows);
    k_scan1<<<NB_E + NB_U, SCAN_B>>>();
    k_scan2<<<1, 128>>>();
    k_scan3<<<NB_E + NB_U, SCAN_B>>>();
    k_fill<<<gE, TB>>>(head, tail, etype, ui_rows, ui_cols, ui_vals);

    k_kg0<<<gKG, TB>>>(entity_emb, weight, out_ent);
    k_ui<0><<<gUI, TB>>>(user_emb, entity_emb, latent, out_usr);
    k_ui<1><<<gUI, TB>>>(user_emb, entity_emb, latent, out_usr);
    k_kg1<<<gKG, TB>>>(weight, out_ent);
}

// round 6
// speedup vs baseline: 1.8621x; 1.0175x over previous
#include <cuda_runtime.h>
#include <math_constants.h>

#define N_ENT   100000
#define N_USR   50000
#define N_EDGE  1000000
#define C       64
#define N_FACT  4
#define N_RELM1 9
#define TEMPR   0.2f
// 1 / (2*sqrt(32))
#define INV_SCALE 0.08838834764831845f

#define SCAN_B  1024
#define NB_E    ((N_ENT + SCAN_B - 1) / SCAN_B)   // 98
#define NB_U    ((N_USR + SCAN_B - 1) / SCAN_B)   // 49

#define KGB     ((N_ENT * 32 + 255) / 256)        // 12500 blocks for KG part
#define UIB     ((N_USR * 32 + 255) / 256)        // 6250 blocks for UI part

// ---------------- scratch (device globals; no allocation) ----------------
__device__ __align__(16) float g_V[N_RELM1 * C];     // W W^T w^T, pre-scaled
__device__ float g_wn2[N_RELM1];
__device__ __align__(16) float g_dw[N_FACT * C];     // softmax(att) @ weight
__device__ __align__(16) float g_entA[N_ENT * C];    // ent after hop0 norm
__device__ __align__(16) float g_usrA[N_USR * C];    // usr after hop0 norm
__device__ float g_mask[N_EDGE];                     // unnormalized e2 per CSR pos
__device__ int g_cntE[N_ENT], g_offE[N_ENT], g_curE[N_ENT];
__device__ int g_cntU[N_USR], g_offU[N_USR], g_curU[N_USR];
__device__ int  g_pkE[N_EDGE];                       // CSR-ordered (tail | type<<20)
__device__ __align__(8) int2 g_uiP[N_EDGE];          // CSR-ordered (col, val bits)
__device__ int g_bsumE[128];
__device__ int g_bsumU[128];

// ---------------- prep body (runs as extra block of scan1) ----------------
__device__ void prep_body(const float* __restrict__ weight,
                          const float* __restrict__ kgW,
                          const float* __restrict__ att,
                          float* __restrict__ out_cor,
                          float* sW, float* sWk) {
    int t = threadIdx.x;
    int nt = blockDim.x;
    for (int i = t; i < C * C; i += nt) sW[i] = kgW[i];
    __syncthreads();
    for (int i = t; i < N_RELM1 * C; i += nt) {
        int r = i / C, k = i % C;
        float s = 0.f;
        for (int c = 0; c < C; c++) s += weight[r * C + c] * sW[c * C + k];
        sWk[i] = s;
    }
    __syncthreads();
    for (int i = t; i < N_RELM1 * C; i += nt) {
        int r = i / C, c = i % C;
        float s = 0.f;
        for (int k = 0; k < C; k++) s += sW[c * C + k] * sWk[r * C + k];
        g_V[i] = s * INV_SCALE;
    }
    if (t < N_RELM1) {
        float s = 0.f;
        for (int c = 0; c < C; c++) { float w = weight[t * C + c]; s += w * w; }
        g_wn2[t] = s;
    }
    if (t >= 32 && t < 32 + N_FACT) {
        int f = t - 32;
        float a[N_RELM1]; float m = -CUDART_INF_F;
        for (int j = 0; j < N_RELM1; j++) { a[j] = att[f * N_RELM1 + j]; m = fmaxf(m, a[j]); }
        float ssum = 0.f;
        for (int j = 0; j < N_RELM1; j++) { a[j] = expf(a[j] - m); ssum += a[j]; }
        for (int j = 0; j < N_RELM1; j++) a[j] /= ssum;
        for (int c = 0; c < C; c++) {
            float s = 0.f;
            for (int j = 0; j < N_RELM1; j++) s += a[j] * weight[j * C + c];
            g_dw[f * C + c] = s;
        }
    }
    if (t == 64) {
        float rowsum[N_FACT];
        for (int f = 0; f < N_FACT; f++) {
            float s = 0.f;
            for (int j = 0; j < N_RELM1; j++) s += att[f * N_RELM1 + j];
            rowsum[f] = s;
        }
        float cor = 0.f;
        for (int r = 0; r < N_RELM1; r++) {
            float ss = 0.f, ttl = 0.f;
            for (int f = 0; f < N_FACT; f++) {
                float v = att[f * N_RELM1 + r];
                ss += v * v; ttl += v * rowsum[f];
            }
            float n = sqrtf(ss);
            float pos = 0.f;
            for (int f = 0; f < N_FACT; f++) {
                float v = att[f * N_RELM1 + r] / n; pos += v * v;
            }
            cor += (ttl - pos) / TEMPR;
        }
        *out_cor = cor;
    }
}

// ---------------- CSR build ----------------
__global__ void k_zcnt() {
    int i = blockIdx.x * blockDim.x + threadIdx.x;
    if (i < N_ENT) g_cntE[i] = 0;
    if (i < N_USR) g_cntU[i] = 0;
}

__global__ void k_count(const int* __restrict__ head, const int* __restrict__ urows) {
    int e = blockIdx.x * blockDim.x + threadIdx.x;
    if (e >= N_EDGE) return;
    atomicAdd(&g_cntE[head[e]], 1);
    atomicAdd(&g_cntU[urows[e]], 1);
}

// scan1: per-block exclusive scan + block sums; last block runs prep instead
__global__ void k_scan1(const float* __restrict__ weight,
                        const float* __restrict__ kgW,
                        const float* __restrict__ att,
                        float* __restrict__ out_cor) {
    __shared__ float sPrep[C * C + N_RELM1 * C];   // 16KB+2.3KB, also reused as int scan buf
    if (blockIdx.x == NB_E + NB_U) {
        prep_body(weight, kgW, att, out_cor, sPrep, sPrep + C * C);
        return;
    }
    int* sh = reinterpret_cast<int*>(sPrep);
    bool isE = blockIdx.x < NB_E;
    int b = isE ? blockIdx.x : blockIdx.x - NB_E;
    int n = isE ? N_ENT : N_USR;
    int* cnt = isE ? g_cntE : g_cntU;
    int* off = isE ? g_offE : g_offU;
    int* bsum = isE ? g_bsumE : g_bsumU;
    int t = threadIdx.x;
    int i = b * SCAN_B + t;
    int v = (i < n) ? cnt[i] : 0;
    sh[t] = v;
    __syncthreads();
    for (int d = 1; d < SCAN_B; d <<= 1) {
        int u = (t >= d) ? sh[t - d] : 0;
        __syncthreads();
        sh[t] += u;
        __syncthreads();
    }
    if (i < n) off[i] = sh[t] - v;   // exclusive within block
    if (t == SCAN_B - 1) bsum[b] = sh[t];
}

// scan3: each block sums preceding block sums itself (<=98 values), applies, inits cursors
__global__ void k_scan3() {
    bool isE = blockIdx.x < NB_E;
    int b = isE ? blockIdx.x : blockIdx.x - NB_E;
    int n = isE ? N_ENT : N_USR;
    int* off = isE ? g_offE : g_offU;
    int* cur = isE ? g_curE : g_curU;
    const int* bsum = isE ? g_bsumE : g_bsumU;
    __shared__ int sbp;
    int t = threadIdx.x;
    if (t < 32) {
        int s = 0;
        for (int j = t; j < b; j += 32) s += bsum[j];
#pragma unroll
        for (int o = 16; o; o >>= 1) s += __shfl_xor_sync(0xffffffffu, s, o);
        if (t == 0) sbp = s;
    }
    __syncthreads();
    int i = b * SCAN_B + t;
    if (i < n) {
        int o = off[i] + sbp;
        off[i] = o;
        cur[i] = o;
    }
}

// fill: materialize edge payloads in CSR order
__global__ void k_fill(const int* __restrict__ head, const int* __restrict__ tail,
                       const int* __restrict__ etype, const int* __restrict__ urows,
                       const int* __restrict__ ucols, const float* __restrict__ uvals) {
    int e = blockIdx.x * blockDim.x + threadIdx.x;
    if (e >= N_EDGE) return;
    int p = atomicAdd(&g_curE[head[e]], 1);
    g_pkE[p] = tail[e] | ((etype[e] - 1) << 20);
    int q = atomicAdd(&g_curU[urows[e]], 1);
    g_uiP[q] = make_int2(ucols[e], __float_as_int(uvals[e]));
}

// ---------------- helpers ----------------
__device__ __forceinline__ float dot4(float4 a, float4 b) {
    return a.x * b.x + a.y * b.y + a.z * b.z + a.w * b.w;
}
__device__ __forceinline__ float red16(float p, unsigned m) {
    p += __shfl_xor_sync(m, p, 1);
    p += __shfl_xor_sync(m, p, 2);
    p += __shfl_xor_sync(m, p, 4);
    p += __shfl_xor_sync(m, p, 8);
    return p;
}

// ---------------- kg0 device body ----------------
__device__ __forceinline__ void kg0_body(int blk, int t,
                                         const float* __restrict__ ent,
                                         float* __restrict__ out_ent,
                                         const float4* sV, const float4* sW,
                                         const float* sWn) {
    int w = blk * 8 + (t >> 5);
    if (w >= N_ENT) return;
    int lane = t & 31, half = lane >> 4, l = lane & 15;
    unsigned hm = 0xFFFFu << (half * 16);
    int off = g_offE[w], deg = g_cntE[w];

    float4 hv = __ldg(&reinterpret_cast<const float4*>(ent)[(size_t)w * 16 + l]);

    // per-relation exp(score): lane r (within each half) holds exp(hv . V_r)
    float me = 0.f;
#pragma unroll
    for (int r = 0; r < N_RELM1; r++) {
        float p = red16(dot4(hv, sV[r * 16 + l]), hm);
        if (l == r) me = expf(p);
    }

    float s1 = 0.f;
#pragma unroll 2
    for (int i = half; i < deg; i += 2) {
        int ty = __ldg(&g_pkE[off + i]) >> 20;
        s1 += __shfl_sync(hm, me, ty, 16);
    }
    __syncwarp();
    s1 += __shfl_xor_sync(0xffffffffu, s1, 16);
    float inv1 = 1.f / (s1 + 1e-16f);

    float4 acc = make_float4(0.f, 0.f, 0.f, 0.f);
#pragma unroll 2
    for (int i = half; i < deg; i += 2) {
        int pk = __ldg(&g_pkE[off + i]);
        int ty = pk >> 20;
        int tl = pk & 0xFFFFF;
        float4 tv = __ldg(&reinterpret_cast<const float4*>(ent)[(size_t)tl * 16 + l]);
        float es = __shfl_sync(hm, me, ty, 16);
        float ht = red16(dot4(hv, tv), hm);
        float rs = es * inv1;
        float e2 = expf(ht + rs * rs * sWn[ty]);
        float4 wv = sW[ty * 16 + l];
        acc.x += e2 * tv.x * wv.x;
        acc.y += e2 * tv.y * wv.y;
        acc.z += e2 * tv.z * wv.z;
        acc.w += e2 * tv.w * wv.w;
        if (l == 0) g_mask[off + i] = e2;
    }
    __syncwarp();
    acc.x += __shfl_xor_sync(0xffffffffu, acc.x, 16);
    acc.y += __shfl_xor_sync(0xffffffffu, acc.y, 16);
    acc.z += __shfl_xor_sync(0xffffffffu, acc.z, 16);
    acc.w += __shfl_xor_sync(0xffffffffu, acc.w, 16);

    float ss = red16(dot4(acc, acc), 0xffffffffu);
    float inv = 1.f / fmaxf(sqrtf(ss), 1e-12f);
    float4 x = make_float4(acc.x * inv, acc.y * inv, acc.z * inv, acc.w * inv);
    if (half == 0) {
        reinterpret_cast<float4*>(g_entA)[(size_t)w * 16 + l] = x;
        float4 o = make_float4(hv.x + x.x, hv.y + x.y, hv.z + x.z, hv.w + x.w);
        reinterpret_cast<float4*>(out_ent)[(size_t)w * 16 + l] = o;
    }
}

// ---------------- kg1 device body ----------------
__device__ __forceinline__ void kg1_body(int blk, int t,
                                         float* __restrict__ out_ent,
                                         const float4* sW) {
    int w = blk * 8 + (t >> 5);
    if (w >= N_ENT) return;
    int lane = t & 31, half = lane >> 4, l = lane & 15;
    int off = g_offE[w], deg = g_cntE[w];

    float4 acc = make_float4(0.f, 0.f, 0.f, 0.f);
#pragma unroll 2
    for (int i = half; i < deg; i += 2) {
        int pk = __ldg(&g_pkE[off + i]);
        float m = __ldg(&g_mask[off + i]);
        int ty = pk >> 20;
        int tl = pk & 0xFFFFF;
        float4 tv = __ldg(&reinterpret_cast<const float4*>(g_entA)[(size_t)tl * 16 + l]);
        float4 wv = sW[ty * 16 + l];
        acc.x += m * tv.x * wv.x;
        acc.y += m * tv.y * wv.y;
        acc.z += m * tv.z * wv.z;
        acc.w += m * tv.w * wv.w;
    }
    __syncwarp();
    acc.x += __shfl_xor_sync(0xffffffffu, acc.x, 16);
    acc.y += __shfl_xor_sync(0xffffffffu, acc.y, 16);
    acc.z += __shfl_xor_sync(0xffffffffu, acc.z, 16);
    acc.w += __shfl_xor_sync(0xffffffffu, acc.w, 16);

    float ss = red16(dot4(acc, acc), 0xffffffffu);
    float inv = 1.f / fmaxf(sqrtf(ss), 1e-12f);
    if (half == 0) {
        float4 o = reinterpret_cast<const float4*>(out_ent)[(size_t)w * 16 + l];
        o.x += acc.x * inv; o.y += acc.y * inv;
        o.z += acc.z * inv; o.w += acc.w * inv;
        reinterpret_cast<float4*>(out_ent)[(size_t)w * 16 + l] = o;
    }
}

// ---------------- ui device body ----------------
template <int HOP>
__device__ __forceinline__ void ui_body(int blk, int t,
                                        const float* __restrict__ user_emb,
                                        const float* __restrict__ entity_emb,
                                        float* __restrict__ out_usr,
                                        const float4* sL, const float4* sD) {
    int u = blk * 8 + (t >> 5);
    if (u >= N_USR) return;
    int lane = t & 31, half = lane >> 4, l = lane & 15;
    unsigned hm = 0xFFFFu << (half * 16);
    const float* usr_src = (HOP == 0) ? user_emb : g_usrA;
    const float* ent_src = (HOP == 0) ? entity_emb : g_entA;

    float4 uv = __ldg(&reinterpret_cast<const float4*>(usr_src)[(size_t)u * 16 + l]);

    float d0 = red16(dot4(uv, sL[0 * 16 + l]), hm);
    float d1 = red16(dot4(uv, sL[1 * 16 + l]), hm);
    float d2 = red16(dot4(uv, sL[2 * 16 + l]), hm);
    float d3 = red16(dot4(uv, sL[3 * 16 + l]), hm);
    float m = fmaxf(fmaxf(d0, d1), fmaxf(d2, d3));
    d0 = expf(d0 - m); d1 = expf(d1 - m); d2 = expf(d2 - m); d3 = expf(d3 - m);
    float invs = 1.f / (d0 + d1 + d2 + d3);
    d0 *= invs; d1 *= invs; d2 *= invs; d3 *= invs;
    float4 a0 = sD[0 * 16 + l], a1 = sD[1 * 16 + l], a2 = sD[2 * 16 + l], a3 = sD[3 * 16 + l];
    float4 mix;
    mix.x = 1.f + d0 * a0.x + d1 * a1.x + d2 * a2.x + d3 * a3.x;
    mix.y = 1.f + d0 * a0.y + d1 * a1.y + d2 * a2.y + d3 * a3.y;
    mix.z = 1.f + d0 * a0.z + d1 * a1.z + d2 * a2.z + d3 * a3.z;
    mix.w = 1.f + d0 * a0.w + d1 * a1.w + d2 * a2.w + d3 * a3.w;

    int off = g_offU[u], deg = g_cntU[u];
    float4 acc = make_float4(0.f, 0.f, 0.f, 0.f);
#pragma unroll 2
    for (int i = half; i < deg; i += 2) {
        int2 p = __ldg(&g_uiP[off + i]);
        float v = __int_as_float(p.y);
        float4 tv = __ldg(&reinterpret_cast<const float4*>(ent_src)[(size_t)p.x * 16 + l]);
        acc.x += v * tv.x; acc.y += v * tv.y;
        acc.z += v * tv.z; acc.w += v * tv.w;
    }
    __syncwarp();
    acc.x += __shfl_xor_sync(0xffffffffu, acc.x, 16);
    acc.y += __shfl_xor_sync(0xffffffffu, acc.y, 16);
    acc.z += __shfl_xor_sync(0xffffffffu, acc.z, 16);
    acc.w += __shfl_xor_sync(0xffffffffu, acc.w, 16);

    float4 x = make_float4(acc.x * mix.x, acc.y * mix.y, acc.z * mix.z, acc.w * mix.w);
    float ss = red16(dot4(x, x), 0xffffffffu);
    float inv = 1.f / fmaxf(sqrtf(ss), 1e-12f);
    x.x *= inv; x.y *= inv; x.z *= inv; x.w *= inv;

    if (half == 0) {
        if (HOP == 0) {
            reinterpret_cast<float4*>(g_usrA)[(size_t)u * 16 + l] = x;
            float4 o = make_float4(uv.x + x.x, uv.y + x.y, uv.z + x.z, uv.w + x.w);
            reinterpret_cast<float4*>(out_usr)[(size_t)u * 16 + l] = o;
        } else {
            float4 o = reinterpret_cast<const float4*>(out_usr)[(size_t)u * 16 + l];
            o.x += x.x; o.y += x.y; o.z += x.z; o.w += x.w;
            reinterpret_cast<float4*>(out_usr)[(size_t)u * 16 + l] = o;
        }
    }
}

// ---------------- fused hop kernels ----------------
__global__ void __launch_bounds__(256) k_fused0(const float* __restrict__ ent,
                                                const float* __restrict__ usr,
                                                const float* __restrict__ latent,
                                                const float* __restrict__ weight,
                                                float* __restrict__ out_ent,
                                                float* __restrict__ out_usr) {
    __shared__ float4 sA[N_RELM1 * 16];   // sV (kg) / sL (ui uses first 4*16)
    __shared__ float4 sB[N_RELM1 * 16];   // sW (kg) / sD (ui uses first 4*16)
    __shared__ float  sWn[N_RELM1];
    int t = threadIdx.x;
    bool isKG = blockIdx.x < KGB;
    if (isKG) {
        for (int i = t; i < N_RELM1 * 16; i += 256) {
            sA[i] = reinterpret_cast<const float4*>(g_V)[i];
            sB[i] = reinterpret_cast<const float4*>(weight)[i];
        }
        if (t < N_RELM1) sWn[t] = g_wn2[t];
    } else {
        for (int i = t; i < N_FACT * 16; i += 256) {
            sA[i] = reinterpret_cast<const float4*>(latent)[i];
            sB[i] = reinterpret_cast<const float4*>(g_dw)[i];
        }
    }
    __syncthreads();
    if (isKG) kg0_body(blockIdx.x, t, ent, out_ent, sA, sB, sWn);
    else      ui_body<0>(blockIdx.x - KGB, t, usr, ent, out_usr, sA, sB);
}

__global__ void __launch_bounds__(256) k_fused1(const float* __restrict__ ent,
                                                const float* __restrict__ usr,
                                                const float* __restrict__ latent,
                                                const float* __restrict__ weight,
                                                float* __restrict__ out_ent,
                                                float* __restrict__ out_usr) {
    __shared__ float4 sA[N_RELM1 * 16];
    __shared__ float4 sB[N_RELM1 * 16];
    int t = threadIdx.x;
    bool isKG = blockIdx.x < KGB;
    if (isKG) {
        for (int i = t; i < N_RELM1 * 16; i += 256)
            sB[i] = reinterpret_cast<const float4*>(weight)[i];
    } else {
        for (int i = t; i < N_FACT * 16; i += 256) {
            sA[i] = reinterpret_cast<const float4*>(latent)[i];
            sB[i] = reinterpret_cast<const float4*>(g_dw)[i];
        }
    }
    __syncthreads();
    if (isKG) kg1_body(blockIdx.x, t, out_ent, sB);
    else      ui_body<1>(blockIdx.x - KGB, t, usr, ent, out_usr, sA, sB);
}

// ---------------- launch ----------------
extern "C" void kernel_launch(void* const* d_in, const int* in_sizes, int n_in,
                              void* d_out, int out_size) {
    const float* user_emb   = (const float*)d_in[0];
    const float* entity_emb = (const float*)d_in[1];
    const float* latent     = (const float*)d_in[2];
    const float* weight     = (const float*)d_in[3];
    const float* att        = (const float*)d_in[4];
    const float* kgW        = (const float*)d_in[5];
    const float* ui_vals    = (const float*)d_in[6];
    const int*   edge_index = (const int*)d_in[7];
    const int*   etype      = (const int*)d_in[8];
    const int*   ui_rows    = (const int*)d_in[9];
    const int*   ui_cols    = (const int*)d_in[10];

    const int* head = edge_index;
    const int* tail = edge_index + N_EDGE;

    float* out     = (float*)d_out;
    float* out_ent = out;
    float* out_usr = out + (size_t)N_ENT * C;
    float* out_cor = out + (size_t)N_ENT * C + (size_t)N_USR * C;

    const int TB = 256;
    dim3 gE((N_EDGE + TB - 1) / TB);
    dim3 gZ((N_ENT + TB - 1) / TB);

    k_zcnt<<<gZ, TB>>>();                                               // 1
    k_count<<<gE, TB>>>(head, ui_rows);                                 // 2
    k_scan1<<<NB_E + NB_U + 1, SCAN_B>>>(weight, kgW, att, out_cor);    // 3 (+prep)
    k_scan3<<<NB_E + NB_U, SCAN_B>>>();                                 // 4
    k_fill<<<gE, TB>>>(head, tail, etype, ui_rows, ui_cols, ui_vals);   // 5
    k_fused0<<<KGB + UIB, TB>>>(entity_emb, user_emb, latent, weight,   // 6 (profiled)
                                out_ent, out_usr);
    k_fused1<<<KGB + UIB, TB>>>(entity_emb, user_emb, latent, weight,   // 7
                                out_ent, out_usr);
}